// round 1
// baseline (speedup 1.0000x reference)
#include <cuda_runtime.h>

#define B_  4
#define S_  2048
#define D_  1024
#define H_  16
#define DK_ 64
#define M_  (B_*S_)

// Scratch (static __device__ arrays; no allocation APIs)
__device__ float g_Q[M_*D_];
__device__ float g_K[M_*D_];
__device__ float g_V[M_*D_];
__device__ float g_X[M_*D_];

// ---------------------------------------------------------------------------
// GEMM with bias: C[m][n] = sum_k A[m][k] * W[n][k] + bias[n]
// A: [M_, 1024] row-major, W: [1024, 1024] row-major (out_features x in)
// OUTMODE 0: scatter to head layout [B,H,S,DK]; OUTMODE 1: natural [M_, D_]
// Block tile 128x128, BK=16, 256 threads, 8x8 per thread.
// ---------------------------------------------------------------------------
template<int OUTMODE>
__global__ __launch_bounds__(256, 2)
void gemm_bias_kernel(const float* __restrict__ A, const float* __restrict__ W,
                      const float* __restrict__ bias, float* __restrict__ out)
{
    __shared__ float As[16][132];   // k-major: As[kk][m], pad 4
    __shared__ float Bs[16][132];   // k-major: Bs[kk][n]

    const int tid  = threadIdx.x;
    const int bm   = blockIdx.y;
    const int bn   = blockIdx.x;
    const int warp = tid >> 5, lane = tid & 31;
    const int wm = warp >> 2, wn = warp & 3;      // 2 x 4 warp grid
    const int lm = lane >> 2, ln = lane & 3;      // 8 x 4 lanes
    const int row0 = wm*64 + lm*4;                // rows: row0+i, row0+32+i
    const int col0 = wn*32 + ln*4;                // cols: col0+j, col0+16+j

    const int lrow = tid >> 2;                    // 0..63
    const int lcg  = tid & 3;                     // float4 column group

    const float* Ap = A + (size_t)(bm*128 + lrow) * D_ + lcg*4;
    const float* Wp = W + (size_t)(bn*128 + lrow) * D_ + lcg*4;

    float acc[8][8];
#pragma unroll
    for (int i=0;i<8;i++)
#pragma unroll
        for (int j=0;j<8;j++) acc[i][j] = 0.f;

    for (int kt = 0; kt < D_; kt += 16) {
#pragma unroll
        for (int r=0; r<2; r++) {
            int rr = r*64 + lrow;
            float4 va = *(const float4*)(Ap + (size_t)r*64*D_ + kt);
            As[lcg*4+0][rr] = va.x;
            As[lcg*4+1][rr] = va.y;
            As[lcg*4+2][rr] = va.z;
            As[lcg*4+3][rr] = va.w;
            float4 vb = *(const float4*)(Wp + (size_t)r*64*D_ + kt);
            Bs[lcg*4+0][rr] = vb.x;
            Bs[lcg*4+1][rr] = vb.y;
            Bs[lcg*4+2][rr] = vb.z;
            Bs[lcg*4+3][rr] = vb.w;
        }
        __syncthreads();
#pragma unroll
        for (int kk=0; kk<16; kk++) {
            float a[8], b[8];
            *(float4*)&a[0] = *(const float4*)&As[kk][row0];
            *(float4*)&a[4] = *(const float4*)&As[kk][row0+32];
            *(float4*)&b[0] = *(const float4*)&Bs[kk][col0];
            *(float4*)&b[4] = *(const float4*)&Bs[kk][col0+16];
#pragma unroll
            for (int i=0;i<8;i++)
#pragma unroll
                for (int j=0;j<8;j++) acc[i][j] = fmaf(a[i], b[j], acc[i][j]);
        }
        __syncthreads();
    }

    // Epilogue: bias + store (float4 per 4-col group)
#pragma unroll
    for (int jh=0; jh<2; jh++) {
        const int c = bn*128 + col0 + jh*16;
        const float4 bv = *(const float4*)(bias + c);
#pragma unroll
        for (int ih=0; ih<2; ih++) {
#pragma unroll
            for (int i=0;i<4;i++) {
                const int m = bm*128 + row0 + ih*32 + i;
                float4 v;
                v.x = acc[ih*4+i][jh*4+0] + bv.x;
                v.y = acc[ih*4+i][jh*4+1] + bv.y;
                v.z = acc[ih*4+i][jh*4+2] + bv.z;
                v.w = acc[ih*4+i][jh*4+3] + bv.w;
                if (OUTMODE == 0) {
                    const int h  = c >> 6;
                    const int dk = c & 63;
                    const int bb = m >> 11;
                    const int ss = m & 2047;
                    *(float4*)(out + ((size_t)((bb*H_ + h)*S_ + ss))*DK_ + dk) = v;
                } else {
                    *(float4*)(out + (size_t)m*D_ + c) = v;
                }
            }
        }
    }
}

// ---------------------------------------------------------------------------
// Flash attention over [BH=64] heads. Q/K/V in [BH][S][64]. Output to g_X in
// merged [B,S,D] layout. BQ = BK = 128, 256 threads, 1 CTA/SM.
// Warp layout for S-GEMM: warp owns 16 q-rows x 128 k-cols -> row softmax
// reductions are pure intra-warp shfl.
// ---------------------------------------------------------------------------
#define QS 132   // padded stride for Qt/Kt/Ps
#define VS 68    // padded stride for Vs

__global__ __launch_bounds__(256, 1)
void flash_attn_kernel(const int* __restrict__ mask)
{
    extern __shared__ float sm[];
    float* Qt = sm;                    // [64][QS]  dk-major (Qt[dk][q])
    float* Kt = Qt + 64*QS;            // [64][QS]  dk-major (Kt[dk][k])
    float* Vs = Kt + 64*QS;            // [128][VS] natural (Vs[k][dk])
    float* Ps = Vs + 128*VS;           // [128][QS] natural (Ps[q][k])

    const int tid = threadIdx.x;
    const int qb  = blockIdx.x;        // 0..15
    const int bh  = blockIdx.y;        // 0..63
    const int q0  = qb*128;

    const float* Qg = g_Q + (size_t)bh * S_ * DK_;
    const float* Kg = g_K + (size_t)bh * S_ * DK_;
    const float* Vg = g_V + (size_t)bh * S_ * DK_;

    const int warp = tid >> 5, lane = tid & 31;
    const int lm = lane >> 3, ln = lane & 7;   // 4 x 8
    const int srow = warp*16 + lm*4;           // this thread's 4 q-rows (local)

    const int lrow = tid >> 2;                 // 0..63
    const int lcg  = tid & 3;

    // Load Q tile (128 x 64), transposed into Qt[dk][q]
#pragma unroll
    for (int r=0;r<8;r++) {
        const int qq  = (r&1)*64 + lrow;
        const int dkg = (r>>1)*4 + lcg;
        float4 v = *(const float4*)(Qg + (size_t)(q0+qq)*DK_ + dkg*4);
        Qt[(dkg*4+0)*QS + qq] = v.x;
        Qt[(dkg*4+1)*QS + qq] = v.y;
        Qt[(dkg*4+2)*QS + qq] = v.z;
        Qt[(dkg*4+3)*QS + qq] = v.w;
    }

    float m_i[4], l_i[4], o[4][8];
#pragma unroll
    for (int i=0;i<4;i++) {
        m_i[i] = -1e30f; l_i[i] = 0.f;
#pragma unroll
        for (int j=0;j<8;j++) o[i][j] = 0.f;
    }

    for (int t0 = 0; t0 < S_; t0 += 128) {
        __syncthreads();   // protect Kt/Vs (and prior-iter Ps readers finished)

        // Load K tile transposed, V tile natural
#pragma unroll
        for (int r=0;r<8;r++) {
            const int kr  = (r&1)*64 + lrow;
            const int dkg = (r>>1)*4 + lcg;
            float4 v = *(const float4*)(Kg + (size_t)(t0+kr)*DK_ + dkg*4);
            Kt[(dkg*4+0)*QS + kr] = v.x;
            Kt[(dkg*4+1)*QS + kr] = v.y;
            Kt[(dkg*4+2)*QS + kr] = v.z;
            Kt[(dkg*4+3)*QS + kr] = v.w;
        }
#pragma unroll
        for (int r=0;r<8;r++) {
            const int idx = tid + 256*r;
            const int kk  = idx >> 4;
            const int dg  = idx & 15;
            *(float4*)&Vs[kk*VS + dg*4] =
                *(const float4*)(Vg + (size_t)(t0+kk)*DK_ + dg*4);
        }
        __syncthreads();

        // S = Q K^T  (thread: 4 q-rows x 16 k-cols; cols = u*32 + ln*4 + v)
        float s[4][16];
#pragma unroll
        for (int i=0;i<4;i++)
#pragma unroll
            for (int c=0;c<16;c++) s[i][c] = 0.f;

#pragma unroll 8
        for (int kk=0; kk<64; kk++) {
            float a[4];
            *(float4*)a = *(const float4*)&Qt[kk*QS + srow];
            float b[16];
#pragma unroll
            for (int u=0;u<4;u++)
                *(float4*)&b[u*4] = *(const float4*)&Kt[kk*QS + u*32 + ln*4];
#pragma unroll
            for (int i=0;i<4;i++)
#pragma unroll
                for (int c=0;c<16;c++) s[i][c] = fmaf(a[i], b[c], s[i][c]);
        }

        // scale + mask + online softmax (row reductions intra-warp over ln)
#pragma unroll
        for (int i=0;i<4;i++) {
            const int* mrow = mask + (size_t)(q0 + srow + i)*S_ + t0;
            float mx = -1e30f;
#pragma unroll
            for (int u=0;u<4;u++) {
                const int4 mv = *(const int4*)(mrow + u*32 + ln*4);
                float v0 = s[i][u*4+0]*0.125f; if (mv.x == 0) v0 = -1e9f;
                float v1 = s[i][u*4+1]*0.125f; if (mv.y == 0) v1 = -1e9f;
                float v2 = s[i][u*4+2]*0.125f; if (mv.z == 0) v2 = -1e9f;
                float v3 = s[i][u*4+3]*0.125f; if (mv.w == 0) v3 = -1e9f;
                s[i][u*4+0]=v0; s[i][u*4+1]=v1; s[i][u*4+2]=v2; s[i][u*4+3]=v3;
                mx = fmaxf(mx, fmaxf(fmaxf(v0,v1), fmaxf(v2,v3)));
            }
#pragma unroll
            for (int off=1; off<8; off<<=1)
                mx = fmaxf(mx, __shfl_xor_sync(0xffffffffu, mx, off));

            const float mnew = fmaxf(m_i[i], mx);
            const float corr = __expf(m_i[i] - mnew);
            float sum = 0.f;
#pragma unroll
            for (int c=0;c<16;c++) {
                const float p = __expf(s[i][c] - mnew);
                s[i][c] = p;
                sum += p;
            }
#pragma unroll
            for (int off=1; off<8; off<<=1)
                sum += __shfl_xor_sync(0xffffffffu, sum, off);

            l_i[i] = l_i[i]*corr + sum;
            m_i[i] = mnew;
#pragma unroll
            for (int j=0;j<8;j++) o[i][j] *= corr;

            // write P row fragment (rows are intra-warp -> __syncwarp below)
#pragma unroll
            for (int u=0;u<4;u++)
                *(float4*)&Ps[(srow+i)*QS + u*32 + ln*4] = *(float4*)&s[i][u*4];
        }
        __syncwarp();   // each warp reads only its own 16 Ps rows

        // O += P V   (thread: 4 q-rows x 8 dk-cols at ln*8)
#pragma unroll 4
        for (int kk=0; kk<128; kk++) {
            float a[4];
#pragma unroll
            for (int i=0;i<4;i++) a[i] = Ps[(srow+i)*QS + kk];
            float b[8];
            *(float4*)&b[0] = *(const float4*)&Vs[kk*VS + ln*8];
            *(float4*)&b[4] = *(const float4*)&Vs[kk*VS + ln*8 + 4];
#pragma unroll
            for (int i=0;i<4;i++)
#pragma unroll
                for (int j=0;j<8;j++) o[i][j] = fmaf(a[i], b[j], o[i][j]);
        }
    }

    // Normalize and write merged output X[b][s][h*64+dk]
    const int bb = bh >> 4, hh = bh & 15;
    float* Xp = g_X + ((size_t)(bb*S_ + q0 + srow))*D_ + hh*DK_ + ln*8;
#pragma unroll
    for (int i=0;i<4;i++) {
        const float inv = 1.f / l_i[i];
        float4 v0, v1;
        v0.x=o[i][0]*inv; v0.y=o[i][1]*inv; v0.z=o[i][2]*inv; v0.w=o[i][3]*inv;
        v1.x=o[i][4]*inv; v1.y=o[i][5]*inv; v1.z=o[i][6]*inv; v1.w=o[i][7]*inv;
        *(float4*)(Xp + (size_t)i*D_)     = v0;
        *(float4*)(Xp + (size_t)i*D_ + 4) = v1;
    }
}

// ---------------------------------------------------------------------------
extern "C" void kernel_launch(void* const* d_in, const int* in_sizes, int n_in,
                              void* d_out, int out_size)
{
    (void)in_sizes; (void)n_in; (void)out_size;
    const float* query = (const float*)d_in[0];
    const float* key_  = (const float*)d_in[1];
    const float* value = (const float*)d_in[2];
    const int*   mask  = (const int*)  d_in[3];
    const float* Wq    = (const float*)d_in[4];
    const float* bq    = (const float*)d_in[5];
    const float* Wk    = (const float*)d_in[6];
    const float* bk    = (const float*)d_in[7];
    const float* Wv    = (const float*)d_in[8];
    const float* bv    = (const float*)d_in[9];
    const float* Wo    = (const float*)d_in[10];
    const float* bo    = (const float*)d_in[11];
    float* out = (float*)d_out;

    const size_t FLASH_SMEM = (size_t)(64*QS + 64*QS + 128*VS + 128*QS) * sizeof(float);
    cudaFuncSetAttribute(flash_attn_kernel,
                         cudaFuncAttributeMaxDynamicSharedMemorySize,
                         (int)FLASH_SMEM);

    void *qp, *kp, *vp, *xp;
    cudaGetSymbolAddress(&qp, g_Q);
    cudaGetSymbolAddress(&kp, g_K);
    cudaGetSymbolAddress(&vp, g_V);
    cudaGetSymbolAddress(&xp, g_X);

    const dim3 ggrid(D_/128, M_/128);   // (8, 64)
    gemm_bias_kernel<0><<<ggrid, 256>>>(query, Wq, bq, (float*)qp);
    gemm_bias_kernel<0><<<ggrid, 256>>>(key_,  Wk, bk, (float*)kp);
    gemm_bias_kernel<0><<<ggrid, 256>>>(value, Wv, bv, (float*)vp);

    flash_attn_kernel<<<dim3(S_/128, B_*H_), 256, FLASH_SMEM>>>(mask);

    gemm_bias_kernel<1><<<ggrid, 256>>>((const float*)xp, Wo, bo, out);
}

// round 4
// speedup vs baseline: 1.2449x; 1.2449x over previous
#include <cuda_runtime.h>
#include <cuda_bf16.h>
#include <cstdint>

#define B_  4
#define S_  2048
#define D_  1024
#define H_  16
#define DK_ 64
#define M_  (B_*S_)

// Scratch (static __device__ arrays; no allocation APIs)
__device__ float g_Q[M_*D_];
__device__ float g_K[M_*D_];
__device__ float g_V[M_*D_];
__device__ float g_X[M_*D_];

// ---------------------------------------------------------------------------
// Helpers (arch-portable PTX only: ldmatrix + mma.sync, sm_80+ baseline)
// ---------------------------------------------------------------------------
__device__ __forceinline__ uint32_t smem_u32(const void* p) {
    uint32_t a;
    asm("{ .reg .u64 t; cvta.to.shared.u64 t, %1; cvt.u32.u64 %0, t; }"
        : "=r"(a) : "l"(p));
    return a;
}
__device__ __forceinline__ void ldsm_x4(uint32_t* r, uint32_t addr) {
    asm volatile("ldmatrix.sync.aligned.m8n8.x4.shared.b16 {%0,%1,%2,%3}, [%4];"
                 : "=r"(r[0]), "=r"(r[1]), "=r"(r[2]), "=r"(r[3]) : "r"(addr));
}
__device__ __forceinline__ void mma_bf16(float* c, const uint32_t* a,
                                         const uint32_t* b) {
    asm volatile(
        "mma.sync.aligned.m16n8k16.row.col.f32.bf16.bf16.f32 "
        "{%0,%1,%2,%3}, {%4,%5,%6,%7}, {%8,%9}, {%0,%1,%2,%3};"
        : "+f"(c[0]), "+f"(c[1]), "+f"(c[2]), "+f"(c[3])
        : "r"(a[0]), "r"(a[1]), "r"(a[2]), "r"(a[3]), "r"(b[0]), "r"(b[1]));
}
__device__ __forceinline__ void sts128(uint32_t addr, uint32_t a, uint32_t b,
                                       uint32_t c, uint32_t d) {
    asm volatile("st.shared.v4.b32 [%0], {%1,%2,%3,%4};"
                 :: "r"(addr), "r"(a), "r"(b), "r"(c), "r"(d) : "memory");
}
// float -> (hi bf16, lo bf16 residual)
__device__ __forceinline__ void split_bf16(float x, uint16_t& h, uint16_t& l) {
    __nv_bfloat16 hb = __float2bfloat16_rn(x);
    float r = x - __bfloat162float(hb);
    __nv_bfloat16 lb = __float2bfloat16_rn(r);
    h = __bfloat16_as_ushort(hb);
    l = __bfloat16_as_ushort(lb);
}

// ---------------------------------------------------------------------------
// bf16-split (3-term) tensor-core GEMM with bias:
//   C[m][n] = sum_k A[m][k] * W[n][k] + bias[n]
// CTA tile 128x128, BK=32, 256 threads (8 warps, 2x4 grid, warp tile 64x32).
// Smem: per stage {Ah, Al, Wh, Wl}, each [128][40] bf16 (pad -> LDSM
// conflict-free). 2 stages. Register-prefetch of next chunk during MMA.
// OUTMODE 0: scatter to head layout [B,H,S,DK]; OUTMODE 1: natural [M_, D_].
// ---------------------------------------------------------------------------
#define GPAD   40                         // bf16 elements per row (32 + 8 pad)
#define GARR   (128 * GPAD * 2)           // 10240 B per array
#define GSTAGE (4 * GARR)                 // 40960 B
#define GSMEM  (2 * GSTAGE)               // 81920 B

template<int OUTMODE>
__global__ __launch_bounds__(256)
void gemm_mma_kernel(const float* __restrict__ A, const float* __restrict__ W,
                     const float* __restrict__ bias, float* __restrict__ out)
{
    extern __shared__ char dsm[];
    const uint32_t sbase = smem_u32(dsm);

    const int tid  = threadIdx.x;
    const int lane = tid & 31;
    const int warp = tid >> 5;
    const int wm   = warp >> 2;           // 0..1
    const int wn   = warp & 3;            // 0..3
    const int bm   = blockIdx.y;
    const int bn   = blockIdx.x;

    // ldmatrix lane->row mappings
    const int arow = (lane & 7) + ((lane >> 3) & 1) * 8;  // A: row within 16
    const int acol = ((lane >> 4) & 1) * 8;               // A: +8 cols (k)
    const int brow = (lane & 7) + ((lane >> 4) & 1) * 8;  // B: n within 16
    const int bcol = ((lane >> 3) & 1) * 8;               // B: +8 cols (k)

    // Loader mapping: row r = tid>>1, 16 consecutive k at cg
    const int r  = tid >> 1;
    const int cg = (tid & 1) * 16;
    const float* Ap = A + (size_t)(bm * 128 + r) * D_ + cg;
    const float* Wp = W + (size_t)(bn * 128 + r) * D_ + cg;
    const uint32_t st_off = (uint32_t)(r * GPAD + cg) * 2;   // byte offset in array

    float acc[4][4][4];
#pragma unroll
    for (int i = 0; i < 4; i++)
#pragma unroll
        for (int j = 0; j < 4; j++)
#pragma unroll
            for (int e = 0; e < 4; e++) acc[i][j][e] = 0.f;

    float4 va[4], vw[4];   // prefetch registers (16 + 16 floats)

    // ---- prologue: load chunk 0, store to stage 0
#pragma unroll
    for (int g = 0; g < 4; g++) va[g] = *(const float4*)(Ap + g * 4);
#pragma unroll
    for (int g = 0; g < 4; g++) vw[g] = *(const float4*)(Wp + g * 4);

    auto store_stage = [&](uint32_t stg) {
        uint32_t hA[8], lA[8], hW[8], lW[8];
#pragma unroll
        for (int g = 0; g < 4; g++) {
            uint16_t h0,h1,h2,h3,l0,l1,l2,l3;
            split_bf16(va[g].x,h0,l0); split_bf16(va[g].y,h1,l1);
            split_bf16(va[g].z,h2,l2); split_bf16(va[g].w,h3,l3);
            hA[g*2+0] = (uint32_t)h0 | ((uint32_t)h1 << 16);
            hA[g*2+1] = (uint32_t)h2 | ((uint32_t)h3 << 16);
            lA[g*2+0] = (uint32_t)l0 | ((uint32_t)l1 << 16);
            lA[g*2+1] = (uint32_t)l2 | ((uint32_t)l3 << 16);
            split_bf16(vw[g].x,h0,l0); split_bf16(vw[g].y,h1,l1);
            split_bf16(vw[g].z,h2,l2); split_bf16(vw[g].w,h3,l3);
            hW[g*2+0] = (uint32_t)h0 | ((uint32_t)h1 << 16);
            hW[g*2+1] = (uint32_t)h2 | ((uint32_t)h3 << 16);
            lW[g*2+0] = (uint32_t)l0 | ((uint32_t)l1 << 16);
            lW[g*2+1] = (uint32_t)l2 | ((uint32_t)l3 << 16);
        }
        const uint32_t a0 = stg + st_off;
        sts128(a0,            hA[0], hA[1], hA[2], hA[3]);
        sts128(a0 + 16,       hA[4], hA[5], hA[6], hA[7]);
        sts128(a0 + GARR,     lA[0], lA[1], lA[2], lA[3]);
        sts128(a0 + GARR+16,  lA[4], lA[5], lA[6], lA[7]);
        sts128(a0 + 2*GARR,   hW[0], hW[1], hW[2], hW[3]);
        sts128(a0 + 2*GARR+16,hW[4], hW[5], hW[6], hW[7]);
        sts128(a0 + 3*GARR,   lW[0], lW[1], lW[2], lW[3]);
        sts128(a0 + 3*GARR+16,lW[4], lW[5], lW[6], lW[7]);
    };

    store_stage(sbase);
    __syncthreads();

    // Per-warp fragment base addresses (byte offsets into an array)
    // A: row = wm*64 + mt*16 + arow, col = ks*16 + acol
    // B: row = wn*32 + ng*16 + brow, col = ks*16 + bcol
    const uint32_t aoff0 = (uint32_t)((wm * 64 + arow) * GPAD + acol) * 2;
    const uint32_t boff0 = (uint32_t)((wn * 32 + brow) * GPAD + bcol) * 2;

    for (int c = 0; c < 32; c++) {
        const uint32_t stg = sbase + (uint32_t)(c & 1) * GSTAGE;

        if (c < 31) {
            const int kt = (c + 1) * 32;
#pragma unroll
            for (int g = 0; g < 4; g++) va[g] = *(const float4*)(Ap + kt + g*4);
#pragma unroll
            for (int g = 0; g < 4; g++) vw[g] = *(const float4*)(Wp + kt + g*4);
        }

        // ---- MMA phase on stage (c&1)
#pragma unroll
        for (int ks = 0; ks < 2; ks++) {
            const uint32_t kb = (uint32_t)(ks * 16 * 2);
            uint32_t aH[4][4], aL[4][4];
#pragma unroll
            for (int mt = 0; mt < 4; mt++) {
                const uint32_t ao = stg + aoff0 + (uint32_t)(mt*16*GPAD)*2 + kb;
                ldsm_x4(aH[mt], ao);
                ldsm_x4(aL[mt], ao + GARR);
            }
            uint32_t bH[2][4], bL[2][4];
#pragma unroll
            for (int ng = 0; ng < 2; ng++) {
                const uint32_t bo = stg + 2*GARR + boff0
                                  + (uint32_t)(ng*16*GPAD)*2 + kb;
                ldsm_x4(bH[ng], bo);
                ldsm_x4(bL[ng], bo + GARR);
            }
#pragma unroll
            for (int mt = 0; mt < 4; mt++) {
#pragma unroll
                for (int nt = 0; nt < 4; nt++) {
                    const uint32_t* bh = &bH[nt >> 1][(nt & 1) * 2];
                    const uint32_t* bl = &bL[nt >> 1][(nt & 1) * 2];
                    mma_bf16(acc[mt][nt], aH[mt], bh);
                    mma_bf16(acc[mt][nt], aH[mt], bl);
                    mma_bf16(acc[mt][nt], aL[mt], bh);
                }
            }
        }

        if (c < 31) store_stage(sbase + (uint32_t)((c + 1) & 1) * GSTAGE);
        __syncthreads();
    }

    // ---- Epilogue: bias + scatter. Thread holds (row=l>>2, col=2*(l&3)).
    const int rl = lane >> 2;
    const int cl = 2 * (lane & 3);
#pragma unroll
    for (int mt = 0; mt < 4; mt++) {
#pragma unroll
        for (int nt = 0; nt < 4; nt++) {
            const int n = bn * 128 + wn * 32 + nt * 8 + cl;
            const float b0 = bias[n], b1 = bias[n + 1];
#pragma unroll
            for (int half = 0; half < 2; half++) {
                const int m = bm * 128 + wm * 64 + mt * 16 + rl + half * 8;
                float2 v;
                v.x = acc[mt][nt][half * 2 + 0] + b0;
                v.y = acc[mt][nt][half * 2 + 1] + b1;
                if (OUTMODE == 0) {
                    const int h  = n >> 6;
                    const int dk = n & 63;
                    const int bb = m >> 11;
                    const int ss = m & 2047;
                    *(float2*)(out + ((size_t)((bb*H_ + h)*S_ + ss))*DK_ + dk) = v;
                } else {
                    *(float2*)(out + (size_t)m * D_ + n) = v;
                }
            }
        }
    }
}

// ---------------------------------------------------------------------------
// Flash attention (SIMT fp32, unchanged from round 1 — passing)
// ---------------------------------------------------------------------------
#define QS 132
#define VS 68

__global__ __launch_bounds__(256, 1)
void flash_attn_kernel(const int* __restrict__ mask)
{
    extern __shared__ float sm[];
    float* Qt = sm;
    float* Kt = Qt + 64*QS;
    float* Vs = Kt + 64*QS;
    float* Ps = Vs + 128*VS;

    const int tid = threadIdx.x;
    const int qb  = blockIdx.x;
    const int bh  = blockIdx.y;
    const int q0  = qb*128;

    const float* Qg = g_Q + (size_t)bh * S_ * DK_;
    const float* Kg = g_K + (size_t)bh * S_ * DK_;
    const float* Vg = g_V + (size_t)bh * S_ * DK_;

    const int warp = tid >> 5, lane = tid & 31;
    const int lm = lane >> 3, ln = lane & 7;
    const int srow = warp*16 + lm*4;

    const int lrow = tid >> 2;
    const int lcg  = tid & 3;

#pragma unroll
    for (int r=0;r<8;r++) {
        const int qq  = (r&1)*64 + lrow;
        const int dkg = (r>>1)*4 + lcg;
        float4 v = *(const float4*)(Qg + (size_t)(q0+qq)*DK_ + dkg*4);
        Qt[(dkg*4+0)*QS + qq] = v.x;
        Qt[(dkg*4+1)*QS + qq] = v.y;
        Qt[(dkg*4+2)*QS + qq] = v.z;
        Qt[(dkg*4+3)*QS + qq] = v.w;
    }

    float m_i[4], l_i[4], o[4][8];
#pragma unroll
    for (int i=0;i<4;i++) {
        m_i[i] = -1e30f; l_i[i] = 0.f;
#pragma unroll
        for (int j=0;j<8;j++) o[i][j] = 0.f;
    }

    for (int t0 = 0; t0 < S_; t0 += 128) {
        __syncthreads();

#pragma unroll
        for (int r=0;r<8;r++) {
            const int kr  = (r&1)*64 + lrow;
            const int dkg = (r>>1)*4 + lcg;
            float4 v = *(const float4*)(Kg + (size_t)(t0+kr)*DK_ + dkg*4);
            Kt[(dkg*4+0)*QS + kr] = v.x;
            Kt[(dkg*4+1)*QS + kr] = v.y;
            Kt[(dkg*4+2)*QS + kr] = v.z;
            Kt[(dkg*4+3)*QS + kr] = v.w;
        }
#pragma unroll
        for (int r=0;r<8;r++) {
            const int idx = tid + 256*r;
            const int kk  = idx >> 4;
            const int dg  = idx & 15;
            *(float4*)&Vs[kk*VS + dg*4] =
                *(const float4*)(Vg + (size_t)(t0+kk)*DK_ + dg*4);
        }
        __syncthreads();

        float s[4][16];
#pragma unroll
        for (int i=0;i<4;i++)
#pragma unroll
            for (int c=0;c<16;c++) s[i][c] = 0.f;

#pragma unroll 8
        for (int kk=0; kk<64; kk++) {
            float a[4];
            *(float4*)a = *(const float4*)&Qt[kk*QS + srow];
            float b[16];
#pragma unroll
            for (int u=0;u<4;u++)
                *(float4*)&b[u*4] = *(const float4*)&Kt[kk*QS + u*32 + ln*4];
#pragma unroll
            for (int i=0;i<4;i++)
#pragma unroll
                for (int c=0;c<16;c++) s[i][c] = fmaf(a[i], b[c], s[i][c]);
        }

#pragma unroll
        for (int i=0;i<4;i++) {
            const int* mrow = mask + (size_t)(q0 + srow + i)*S_ + t0;
            float mx = -1e30f;
#pragma unroll
            for (int u=0;u<4;u++) {
                const int4 mv = *(const int4*)(mrow + u*32 + ln*4);
                float v0 = s[i][u*4+0]*0.125f; if (mv.x == 0) v0 = -1e9f;
                float v1 = s[i][u*4+1]*0.125f; if (mv.y == 0) v1 = -1e9f;
                float v2 = s[i][u*4+2]*0.125f; if (mv.z == 0) v2 = -1e9f;
                float v3 = s[i][u*4+3]*0.125f; if (mv.w == 0) v3 = -1e9f;
                s[i][u*4+0]=v0; s[i][u*4+1]=v1; s[i][u*4+2]=v2; s[i][u*4+3]=v3;
                mx = fmaxf(mx, fmaxf(fmaxf(v0,v1), fmaxf(v2,v3)));
            }
#pragma unroll
            for (int off=1; off<8; off<<=1)
                mx = fmaxf(mx, __shfl_xor_sync(0xffffffffu, mx, off));

            const float mnew = fmaxf(m_i[i], mx);
            const float corr = __expf(m_i[i] - mnew);
            float sum = 0.f;
#pragma unroll
            for (int c=0;c<16;c++) {
                const float p = __expf(s[i][c] - mnew);
                s[i][c] = p;
                sum += p;
            }
#pragma unroll
            for (int off=1; off<8; off<<=1)
                sum += __shfl_xor_sync(0xffffffffu, sum, off);

            l_i[i] = l_i[i]*corr + sum;
            m_i[i] = mnew;
#pragma unroll
            for (int j=0;j<8;j++) o[i][j] *= corr;

#pragma unroll
            for (int u=0;u<4;u++)
                *(float4*)&Ps[(srow+i)*QS + u*32 + ln*4] = *(float4*)&s[i][u*4];
        }
        __syncwarp();

#pragma unroll 4
        for (int kk=0; kk<128; kk++) {
            float a[4];
#pragma unroll
            for (int i=0;i<4;i++) a[i] = Ps[(srow+i)*QS + kk];
            float b[8];
            *(float4*)&b[0] = *(const float4*)&Vs[kk*VS + ln*8];
            *(float4*)&b[4] = *(const float4*)&Vs[kk*VS + ln*8 + 4];
#pragma unroll
            for (int i=0;i<4;i++)
#pragma unroll
                for (int j=0;j<8;j++) o[i][j] = fmaf(a[i], b[j], o[i][j]);
        }
    }

    const int bb = bh >> 4, hh = bh & 15;
    float* Xp = g_X + ((size_t)(bb*S_ + q0 + srow))*D_ + hh*DK_ + ln*8;
#pragma unroll
    for (int i=0;i<4;i++) {
        const float inv = 1.f / l_i[i];
        float4 v0, v1;
        v0.x=o[i][0]*inv; v0.y=o[i][1]*inv; v0.z=o[i][2]*inv; v0.w=o[i][3]*inv;
        v1.x=o[i][4]*inv; v1.y=o[i][5]*inv; v1.z=o[i][6]*inv; v1.w=o[i][7]*inv;
        *(float4*)(Xp + (size_t)i*D_)     = v0;
        *(float4*)(Xp + (size_t)i*D_ + 4) = v1;
    }
}

// ---------------------------------------------------------------------------
extern "C" void kernel_launch(void* const* d_in, const int* in_sizes, int n_in,
                              void* d_out, int out_size)
{
    (void)in_sizes; (void)n_in; (void)out_size;
    const float* query = (const float*)d_in[0];
    const float* key_  = (const float*)d_in[1];
    const float* value = (const float*)d_in[2];
    const int*   mask  = (const int*)  d_in[3];
    const float* Wq    = (const float*)d_in[4];
    const float* bq    = (const float*)d_in[5];
    const float* Wk    = (const float*)d_in[6];
    const float* bk    = (const float*)d_in[7];
    const float* Wv    = (const float*)d_in[8];
    const float* bv    = (const float*)d_in[9];
    const float* Wo    = (const float*)d_in[10];
    const float* bo    = (const float*)d_in[11];
    float* out = (float*)d_out;

    const size_t FLASH_SMEM = (size_t)(64*QS + 64*QS + 128*VS + 128*QS) * sizeof(float);
    cudaFuncSetAttribute(flash_attn_kernel,
                         cudaFuncAttributeMaxDynamicSharedMemorySize,
                         (int)FLASH_SMEM);
    cudaFuncSetAttribute(gemm_mma_kernel<0>,
                         cudaFuncAttributeMaxDynamicSharedMemorySize, GSMEM);
    cudaFuncSetAttribute(gemm_mma_kernel<1>,
                         cudaFuncAttributeMaxDynamicSharedMemorySize, GSMEM);

    void *qp, *kp, *vp, *xp;
    cudaGetSymbolAddress(&qp, g_Q);
    cudaGetSymbolAddress(&kp, g_K);
    cudaGetSymbolAddress(&vp, g_V);
    cudaGetSymbolAddress(&xp, g_X);

    const dim3 ggrid(D_/128, M_/128);   // (8, 64)
    gemm_mma_kernel<0><<<ggrid, 256, GSMEM>>>(query, Wq, bq, (float*)qp);
    gemm_mma_kernel<0><<<ggrid, 256, GSMEM>>>(key_,  Wk, bk, (float*)kp);
    gemm_mma_kernel<0><<<ggrid, 256, GSMEM>>>(value, Wv, bv, (float*)vp);

    flash_attn_kernel<<<dim3(S_/128, B_*H_), 256, FLASH_SMEM>>>(mask);

    gemm_mma_kernel<1><<<ggrid, 256, GSMEM>>>((const float*)xp, Wo, bo, out);
}

// round 7
// speedup vs baseline: 2.0368x; 1.6361x over previous
#include <cuda_runtime.h>
#include <cuda_bf16.h>
#include <cstdint>

#define B_  4
#define S_  2048
#define D_  1024
#define H_  16
#define DK_ 64
#define M_  (B_*S_)

// ---------------------------------------------------------------------------
// Scratch (bf16 bit-patterns held in ushort arrays; no allocation APIs)
// ---------------------------------------------------------------------------
__device__ unsigned short c_qh[M_*D_], c_ql[M_*D_];   // converted query
__device__ unsigned short c_kh[M_*D_], c_kl[M_*D_];   // converted key
__device__ unsigned short c_vh[M_*D_], c_vl[M_*D_];   // converted value
__device__ unsigned short w_qh[D_*D_], w_ql[D_*D_];
__device__ unsigned short w_kh[D_*D_], w_kl[D_*D_];
__device__ unsigned short w_vh[D_*D_], w_vl[D_*D_];
__device__ unsigned short w_oh[D_*D_], w_ol[D_*D_];
__device__ unsigned short p_qh[M_*D_], p_ql[M_*D_];   // Q proj, [bh][s][dk]
__device__ unsigned short p_kh[M_*D_], p_kl[M_*D_];   // K proj, [bh][s][dk]
__device__ unsigned short p_vth[M_*D_], p_vtl[M_*D_]; // V proj, [bh][dk][s]
__device__ unsigned short x_h[M_*D_], x_l[M_*D_];     // attn out, [b][s][d]

// ---------------------------------------------------------------------------
// Helpers (arch-portable PTX: ldmatrix + mma.sync)
// ---------------------------------------------------------------------------
__device__ __forceinline__ uint32_t smem_u32(const void* p) {
    uint32_t a;
    asm("{ .reg .u64 t; cvta.to.shared.u64 t, %1; cvt.u32.u64 %0, t; }"
        : "=r"(a) : "l"(p));
    return a;
}
__device__ __forceinline__ void ldsm_x4(uint32_t* r, uint32_t addr) {
    asm volatile("ldmatrix.sync.aligned.m8n8.x4.shared.b16 {%0,%1,%2,%3}, [%4];"
                 : "=r"(r[0]), "=r"(r[1]), "=r"(r[2]), "=r"(r[3]) : "r"(addr));
}
__device__ __forceinline__ void mma_bf16(float* c, const uint32_t* a,
                                         const uint32_t* b) {
    asm volatile(
        "mma.sync.aligned.m16n8k16.row.col.f32.bf16.bf16.f32 "
        "{%0,%1,%2,%3}, {%4,%5,%6,%7}, {%8,%9}, {%0,%1,%2,%3};"
        : "+f"(c[0]), "+f"(c[1]), "+f"(c[2]), "+f"(c[3])
        : "r"(a[0]), "r"(a[1]), "r"(a[2]), "r"(a[3]), "r"(b[0]), "r"(b[1]));
}
__device__ __forceinline__ void sts128(uint32_t addr, uint4 v) {
    asm volatile("st.shared.v4.b32 [%0], {%1,%2,%3,%4};"
                 :: "r"(addr), "r"(v.x), "r"(v.y), "r"(v.z), "r"(v.w)
                 : "memory");
}
__device__ __forceinline__ void split_bf16(float x, uint16_t& h, uint16_t& l) {
    __nv_bfloat16 hb = __float2bfloat16_rn(x);
    float r = x - __bfloat162float(hb);
    __nv_bfloat16 lb = __float2bfloat16_rn(r);
    h = __bfloat16_as_ushort(hb);
    l = __bfloat16_as_ushort(lb);
}
__device__ __forceinline__ void split_pack2(float x, float y,
                                            uint32_t& hp, uint32_t& lp) {
    uint16_t hx, lx, hy, ly;
    split_bf16(x, hx, lx);
    split_bf16(y, hy, ly);
    hp = (uint32_t)hx | ((uint32_t)hy << 16);
    lp = (uint32_t)lx | ((uint32_t)ly << 16);
}

// ---------------------------------------------------------------------------
// Convert: fp32 -> (hi, lo) bf16 arrays
// ---------------------------------------------------------------------------
__global__ void convert_split_kernel(const float* __restrict__ in,
                                     unsigned short* __restrict__ hi,
                                     unsigned short* __restrict__ lo, int n4)
{
    const int stride = gridDim.x * blockDim.x;
    for (int i = blockIdx.x * blockDim.x + threadIdx.x; i < n4; i += stride) {
        float4 v = ((const float4*)in)[i];
        uint32_t h0, l0, h1, l1;
        split_pack2(v.x, v.y, h0, l0);
        split_pack2(v.z, v.w, h1, l1);
        ((uint2*)hi)[i] = make_uint2(h0, h1);
        ((uint2*)lo)[i] = make_uint2(l0, l1);
    }
}

// ---------------------------------------------------------------------------
// bf16-split (3-term) tensor-core GEMM with bias, pre-split inputs:
//   C[m][n] = sum_k A[m][k] * W[n][k] + bias[n]
// CTA 128x128, BK=32, 8 warps (2x4), warp tile 64x32, 2-stage smem.
// OUTMODE 0: bf16 h/l head layout [bh][s][dk]
// OUTMODE 1: bf16 h/l transposed head layout [bh][dk][s]
// OUTMODE 2: fp32 natural [m][n]
// ---------------------------------------------------------------------------
#define GPAD   40                        // bf16 per row (32 + 8 pad)
#define GROWB  80                        // row bytes
#define GARR   (128 * GROWB)             // 10240 B
#define GSTAGE (4 * GARR)
#define GSMEM  (2 * GSTAGE)              // 81920 B

template<int OUTMODE>
__global__ __launch_bounds__(256)
void gemm_bf16_kernel(const unsigned short* __restrict__ Ah,
                      const unsigned short* __restrict__ Al,
                      const unsigned short* __restrict__ Wh,
                      const unsigned short* __restrict__ Wl,
                      const float* __restrict__ bias,
                      float* __restrict__ out32,
                      unsigned short* __restrict__ outh,
                      unsigned short* __restrict__ outl)
{
    extern __shared__ char dsm[];
    const uint32_t sbase = smem_u32(dsm);

    const int tid  = threadIdx.x;
    const int lane = tid & 31;
    const int warp = tid >> 5;
    const int wm   = warp >> 2;
    const int wn   = warp & 3;
    const int bm   = blockIdx.y;
    const int bn   = blockIdx.x;

    const int arow = (lane & 7) + ((lane >> 3) & 1) * 8;
    const int acol = ((lane >> 4) & 1) * 8;
    const int brow = (lane & 7) + ((lane >> 4) & 1) * 8;
    const int bcol = ((lane >> 3) & 1) * 8;

    // Loader: row = tid>>1, half = tid&1 covers 16 bf16 (32B)
    const int r    = tid >> 1;
    const int half = tid & 1;
    const unsigned short* Ap = Ah + (size_t)(bm * 128 + r) * D_ + half * 16;
    const unsigned short* Alp= Al + (size_t)(bm * 128 + r) * D_ + half * 16;
    const unsigned short* Wp = Wh + (size_t)(bn * 128 + r) * D_ + half * 16;
    const unsigned short* Wlp= Wl + (size_t)(bn * 128 + r) * D_ + half * 16;
    const uint32_t st_off = (uint32_t)(r * GROWB + half * 32);

    float acc[4][4][4];
#pragma unroll
    for (int i = 0; i < 4; i++)
#pragma unroll
        for (int j = 0; j < 4; j++)
#pragma unroll
            for (int e = 0; e < 4; e++) acc[i][j][e] = 0.f;

    uint4 pf[8];
    auto prefetch = [&](int kt) {
        pf[0] = *(const uint4*)(Ap + kt);
        pf[1] = *(const uint4*)(Ap + kt + 8);
        pf[2] = *(const uint4*)(Alp + kt);
        pf[3] = *(const uint4*)(Alp + kt + 8);
        pf[4] = *(const uint4*)(Wp + kt);
        pf[5] = *(const uint4*)(Wp + kt + 8);
        pf[6] = *(const uint4*)(Wlp + kt);
        pf[7] = *(const uint4*)(Wlp + kt + 8);
    };
    auto store_stage = [&](uint32_t stg) {
        const uint32_t a0 = stg + st_off;
        sts128(a0,             pf[0]);
        sts128(a0 + 16,        pf[1]);
        sts128(a0 + GARR,      pf[2]);
        sts128(a0 + GARR + 16, pf[3]);
        sts128(a0 + 2*GARR,      pf[4]);
        sts128(a0 + 2*GARR + 16, pf[5]);
        sts128(a0 + 3*GARR,      pf[6]);
        sts128(a0 + 3*GARR + 16, pf[7]);
    };

    prefetch(0);
    store_stage(sbase);
    __syncthreads();

    const uint32_t aoff0 = (uint32_t)((wm * 64 + arow) * GROWB + acol * 2);
    const uint32_t boff0 = (uint32_t)((wn * 32 + brow) * GROWB + bcol * 2);

    for (int c = 0; c < 32; c++) {
        const uint32_t stg = sbase + (uint32_t)(c & 1) * GSTAGE;
        if (c < 31) prefetch((c + 1) * 32);

#pragma unroll
        for (int ks = 0; ks < 2; ks++) {
            const uint32_t kb = (uint32_t)(ks * 32);
            uint32_t aH[4][4], aL[4][4];
#pragma unroll
            for (int mt = 0; mt < 4; mt++) {
                const uint32_t ao = stg + aoff0 + (uint32_t)(mt*16*GROWB) + kb;
                ldsm_x4(aH[mt], ao);
                ldsm_x4(aL[mt], ao + GARR);
            }
            uint32_t bH[2][4], bL[2][4];
#pragma unroll
            for (int ng = 0; ng < 2; ng++) {
                const uint32_t bo = stg + 2*GARR + boff0
                                  + (uint32_t)(ng*16*GROWB) + kb;
                ldsm_x4(bH[ng], bo);
                ldsm_x4(bL[ng], bo + GARR);
            }
#pragma unroll
            for (int mt = 0; mt < 4; mt++) {
#pragma unroll
                for (int nt = 0; nt < 4; nt++) {
                    const uint32_t* bh = &bH[nt >> 1][(nt & 1) * 2];
                    const uint32_t* bl = &bL[nt >> 1][(nt & 1) * 2];
                    mma_bf16(acc[mt][nt], aH[mt], bh);
                    mma_bf16(acc[mt][nt], aH[mt], bl);
                    mma_bf16(acc[mt][nt], aL[mt], bh);
                }
            }
        }

        if (c < 31) store_stage(sbase + (uint32_t)((c + 1) & 1) * GSTAGE);
        __syncthreads();
    }

    // Epilogue
    const int rl = lane >> 2;
    const int cl = 2 * (lane & 3);
#pragma unroll
    for (int mt = 0; mt < 4; mt++) {
#pragma unroll
        for (int nt = 0; nt < 4; nt++) {
            const int n = bn * 128 + wn * 32 + nt * 8 + cl;
            const float b0 = bias[n], b1 = bias[n + 1];
#pragma unroll
            for (int hf = 0; hf < 2; hf++) {
                const int m = bm * 128 + wm * 64 + mt * 16 + rl + hf * 8;
                const float vx = acc[mt][nt][hf * 2 + 0] + b0;
                const float vy = acc[mt][nt][hf * 2 + 1] + b1;
                const int h  = n >> 6;
                const int dk = n & 63;
                const int bb = m >> 11;
                const int ss = m & 2047;
                if (OUTMODE == 2) {
                    *(float2*)(out32 + (size_t)m * D_ + n) = make_float2(vx, vy);
                } else if (OUTMODE == 0) {
                    const size_t idx = ((size_t)((bb*H_ + h)*S_ + ss))*DK_ + dk;
                    uint32_t hp, lp;
                    split_pack2(vx, vy, hp, lp);
                    *(uint32_t*)(outh + idx) = hp;
                    *(uint32_t*)(outl + idx) = lp;
                } else {
                    const size_t idx = ((size_t)((bb*H_ + h)*DK_ + dk))*S_ + ss;
                    uint16_t hx, lx, hy, ly;
                    split_bf16(vx, hx, lx);
                    split_bf16(vy, hy, ly);
                    outh[idx] = hx;        outl[idx] = lx;
                    outh[idx + S_] = hy;   outl[idx + S_] = ly;
                }
            }
        }
    }
}

// ---------------------------------------------------------------------------
// Tensor-core flash attention.
// Grid (qb=16, bh=64), 256 threads (8 warps), warp owns 16 q-rows.
// S = Q K^T (3-term bf16), online softmax (quad-shfl), O = P V (3-term).
// Q/K smem [128][72] bf16 h+l; Vt smem [64][136]; Ps smem [128][136] h+l.
// ---------------------------------------------------------------------------
#define QKROWB 144                       // 72 bf16
#define VTROWB 272                       // 136 bf16
#define QK_BYTES (128 * QKROWB)          // 18432
#define VT_BYTES (64 * VTROWB)           // 17408
#define PS_BYTES (128 * VTROWB)          // 34816
#define F_QH 0
#define F_QL (F_QH + QK_BYTES)
#define F_KH (F_QL + QK_BYTES)
#define F_KL (F_KH + QK_BYTES)
#define F_VH (F_KL + QK_BYTES)
#define F_VL (F_VH + VT_BYTES)
#define F_PH (F_VL + VT_BYTES)
#define F_PL (F_PH + PS_BYTES)
#define F_SMEM (F_PL + PS_BYTES)         // 178176 B

__global__ __launch_bounds__(256, 1)
void flash_mma_kernel(const int* __restrict__ mask)
{
    extern __shared__ char dsm[];
    const uint32_t sb = smem_u32(dsm);

    const int tid  = threadIdx.x;
    const int lane = tid & 31;
    const int warp = tid >> 5;
    const int qb   = blockIdx.x;
    const int bh   = blockIdx.y;
    const int q0   = qb * 128;

    const int arow = (lane & 7) + ((lane >> 3) & 1) * 8;
    const int acol = ((lane >> 4) & 1) * 8;
    const int brow = (lane & 7) + ((lane >> 4) & 1) * 8;
    const int bcol = ((lane >> 3) & 1) * 8;
    const int ln2  = lane & 3;
    const int r0   = warp * 16 + (lane >> 2);   // thread's rows: r0, r0+8

    const unsigned short* Qhp = p_qh + (size_t)bh * S_ * DK_;
    const unsigned short* Qlp = p_ql + (size_t)bh * S_ * DK_;
    const unsigned short* Khp = p_kh + (size_t)bh * S_ * DK_;
    const unsigned short* Klp = p_kl + (size_t)bh * S_ * DK_;
    const unsigned short* Vhp = p_vth + (size_t)bh * DK_ * S_;
    const unsigned short* Vlp = p_vtl + (size_t)bh * DK_ * S_;

    // ---- load Q tile (once): row = tid>>1, seg = tid&1 covers 64B
    {
        const int row = tid >> 1, seg = tid & 1;
        const size_t g = (size_t)(q0 + row) * DK_ + seg * 32;
        const uint32_t s = sb + row * QKROWB + seg * 64;
#pragma unroll
        for (int i = 0; i < 4; i++) {
            sts128(s + F_QH + i*16, *(const uint4*)(Qhp + g + i*8));
            sts128(s + F_QL + i*16, *(const uint4*)(Qlp + g + i*8));
        }
    }

    float m0 = -1e30f, m1 = -1e30f, l0 = 0.f, l1 = 0.f;
    float oacc[8][4];
#pragma unroll
    for (int j = 0; j < 8; j++)
#pragma unroll
        for (int e = 0; e < 4; e++) oacc[j][e] = 0.f;

    for (int t0 = 0; t0 < S_; t0 += 128) {
        __syncthreads();
        // ---- load K tile [128][64] and Vt tile [64][128]
        {
            const int row = tid >> 1, seg = tid & 1;
            const size_t g = (size_t)(t0 + row) * DK_ + seg * 32;
            const uint32_t s = sb + row * QKROWB + seg * 64;
#pragma unroll
            for (int i = 0; i < 4; i++) {
                sts128(s + F_KH + i*16, *(const uint4*)(Khp + g + i*8));
                sts128(s + F_KL + i*16, *(const uint4*)(Klp + g + i*8));
            }
            const int vrow = tid >> 2, vseg = tid & 3;
            const size_t gv = (size_t)vrow * S_ + t0 + vseg * 32;
            const uint32_t sv = sb + vrow * VTROWB + vseg * 64;
#pragma unroll
            for (int i = 0; i < 4; i++) {
                sts128(sv + F_VH + i*16, *(const uint4*)(Vhp + gv + i*8));
                sts128(sv + F_VL + i*16, *(const uint4*)(Vlp + gv + i*8));
            }
        }
        __syncthreads();

        // ---- S = Q K^T : sacc[16 n8-tiles][4]
        float sacc[16][4];
#pragma unroll
        for (int j = 0; j < 16; j++)
#pragma unroll
            for (int e = 0; e < 4; e++) sacc[j][e] = 0.f;

#pragma unroll
        for (int ks = 0; ks < 4; ks++) {
            const uint32_t kb = (uint32_t)(ks * 32);
            uint32_t aH[4], aL[4];
            const uint32_t ao = sb + (warp*16 + arow) * QKROWB + acol*2 + kb;
            ldsm_x4(aH, ao + F_QH);
            ldsm_x4(aL, ao + F_QL);
#pragma unroll
            for (int j16 = 0; j16 < 8; j16++) {
                uint32_t bH[4], bL[4];
                const uint32_t bo = sb + (j16*16 + brow) * QKROWB + bcol*2 + kb;
                ldsm_x4(bH, bo + F_KH);
                ldsm_x4(bL, bo + F_KL);
#pragma unroll
                for (int hf = 0; hf < 2; hf++) {
                    float* a2 = sacc[j16*2 + hf];
                    mma_bf16(a2, aH, &bH[hf*2]);
                    mma_bf16(a2, aH, &bL[hf*2]);
                    mma_bf16(a2, aL, &bH[hf*2]);
                }
            }
        }

        // ---- softmax (rows r0 / r0+8), mask, P -> smem (hi/lo)
#pragma unroll
        for (int p = 0; p < 2; p++) {
            const int r  = r0 + p * 8;
            const int eb = p * 2;
            const int* mrow = mask + (size_t)(q0 + r) * S_ + t0 + 2*ln2;

            float mx = -1e30f;
#pragma unroll
            for (int j = 0; j < 16; j++) {
                const int2 mv = *(const int2*)(mrow + j * 8);
                float v0 = sacc[j][eb+0] * 0.125f; if (mv.x == 0) v0 = -1e9f;
                float v1 = sacc[j][eb+1] * 0.125f; if (mv.y == 0) v1 = -1e9f;
                sacc[j][eb+0] = v0;
                sacc[j][eb+1] = v1;
                mx = fmaxf(mx, fmaxf(v0, v1));
            }
            mx = fmaxf(mx, __shfl_xor_sync(0xffffffffu, mx, 1));
            mx = fmaxf(mx, __shfl_xor_sync(0xffffffffu, mx, 2));

            const float mp   = (p == 0) ? m0 : m1;
            const float mnew = fmaxf(mp, mx);
            const float corr = __expf(mp - mnew);
            float sum = 0.f;
            const uint32_t psa = sb + r * VTROWB + 4*ln2;
#pragma unroll
            for (int j = 0; j < 16; j++) {
                const float p0 = __expf(sacc[j][eb+0] - mnew);
                const float p1 = __expf(sacc[j][eb+1] - mnew);
                sum += p0 + p1;
                uint32_t hp, lp;
                split_pack2(p0, p1, hp, lp);
                asm volatile("st.shared.b32 [%0], %1;"
                             :: "r"(psa + F_PH + j*16), "r"(hp) : "memory");
                asm volatile("st.shared.b32 [%0], %1;"
                             :: "r"(psa + F_PL + j*16), "r"(lp) : "memory");
            }
            sum += __shfl_xor_sync(0xffffffffu, sum, 1);
            sum += __shfl_xor_sync(0xffffffffu, sum, 2);

            if (p == 0) { l0 = l0 * corr + sum; m0 = mnew; }
            else        { l1 = l1 * corr + sum; m1 = mnew; }
#pragma unroll
            for (int j = 0; j < 8; j++) {
                oacc[j][eb+0] *= corr;
                oacc[j][eb+1] *= corr;
            }
        }
        __syncwarp();

        // ---- O += P V : oacc[8 n8-tiles][4], contraction over kv=128
#pragma unroll
        for (int ks = 0; ks < 8; ks++) {
            const uint32_t kb = (uint32_t)(ks * 32);
            uint32_t aH[4], aL[4];
            const uint32_t ao = sb + (warp*16 + arow) * VTROWB + acol*2 + kb;
            ldsm_x4(aH, ao + F_PH);
            ldsm_x4(aL, ao + F_PL);
#pragma unroll
            for (int j16 = 0; j16 < 4; j16++) {
                uint32_t bH[4], bL[4];
                const uint32_t bo = sb + (j16*16 + brow) * VTROWB + bcol*2 + kb;
                ldsm_x4(bH, bo + F_VH);
                ldsm_x4(bL, bo + F_VL);
#pragma unroll
                for (int hf = 0; hf < 2; hf++) {
                    float* a2 = oacc[j16*2 + hf];
                    mma_bf16(a2, aH, &bH[hf*2]);
                    mma_bf16(a2, aH, &bL[hf*2]);
                    mma_bf16(a2, aL, &bH[hf*2]);
                }
            }
        }
    }

    // ---- epilogue: X[b][s][h*64+dk] bf16 hi/lo
    const int bb = bh >> 4, hh = bh & 15;
#pragma unroll
    for (int p = 0; p < 2; p++) {
        const int r   = r0 + p * 8;
        const int eb  = p * 2;
        const float inv = 1.f / ((p == 0) ? l0 : l1);
        const size_t base = ((size_t)(bb * S_ + q0 + r)) * D_ + hh * DK_ + 2*ln2;
#pragma unroll
        for (int j = 0; j < 8; j++) {
            uint32_t hp, lp;
            split_pack2(oacc[j][eb+0] * inv, oacc[j][eb+1] * inv, hp, lp);
            *(uint32_t*)(x_h + base + j*8) = hp;
            *(uint32_t*)(x_l + base + j*8) = lp;
        }
    }
}

// ---------------------------------------------------------------------------
extern "C" void kernel_launch(void* const* d_in, const int* in_sizes, int n_in,
                              void* d_out, int out_size)
{
    (void)in_sizes; (void)n_in; (void)out_size;
    const float* query = (const float*)d_in[0];
    const float* key_  = (const float*)d_in[1];
    const float* value = (const float*)d_in[2];
    const int*   mask  = (const int*)  d_in[3];
    const float* Wq    = (const float*)d_in[4];
    const float* bq    = (const float*)d_in[5];
    const float* Wk    = (const float*)d_in[6];
    const float* bk    = (const float*)d_in[7];
    const float* Wv    = (const float*)d_in[8];
    const float* bv    = (const float*)d_in[9];
    const float* Wo    = (const float*)d_in[10];
    const float* bo    = (const float*)d_in[11];
    float* out = (float*)d_out;

    cudaFuncSetAttribute(flash_mma_kernel,
                         cudaFuncAttributeMaxDynamicSharedMemorySize, F_SMEM);
    cudaFuncSetAttribute(gemm_bf16_kernel<0>,
                         cudaFuncAttributeMaxDynamicSharedMemorySize, GSMEM);
    cudaFuncSetAttribute(gemm_bf16_kernel<1>,
                         cudaFuncAttributeMaxDynamicSharedMemorySize, GSMEM);
    cudaFuncSetAttribute(gemm_bf16_kernel<2>,
                         cudaFuncAttributeMaxDynamicSharedMemorySize, GSMEM);

    // Resolve scratch symbol addresses
    void *cqh,*cql,*ckh,*ckl,*cvh,*cvl;
    void *wqh,*wql,*wkh,*wkl,*wvh,*wvl,*woh,*wol;
    void *pqh,*pql,*pkh,*pkl,*pvth,*pvtl,*xh,*xl;
    cudaGetSymbolAddress(&cqh, c_qh); cudaGetSymbolAddress(&cql, c_ql);
    cudaGetSymbolAddress(&ckh, c_kh); cudaGetSymbolAddress(&ckl, c_kl);
    cudaGetSymbolAddress(&cvh, c_vh); cudaGetSymbolAddress(&cvl, c_vl);
    cudaGetSymbolAddress(&wqh, w_qh); cudaGetSymbolAddress(&wql, w_ql);
    cudaGetSymbolAddress(&wkh, w_kh); cudaGetSymbolAddress(&wkl, w_kl);
    cudaGetSymbolAddress(&wvh, w_vh); cudaGetSymbolAddress(&wvl, w_vl);
    cudaGetSymbolAddress(&woh, w_oh); cudaGetSymbolAddress(&wol, w_ol);
    cudaGetSymbolAddress(&pqh, p_qh); cudaGetSymbolAddress(&pql, p_ql);
    cudaGetSymbolAddress(&pkh, p_kh); cudaGetSymbolAddress(&pkl, p_kl);
    cudaGetSymbolAddress(&pvth, p_vth); cudaGetSymbolAddress(&pvtl, p_vtl);
    cudaGetSymbolAddress(&xh, x_h); cudaGetSymbolAddress(&xl, x_l);

    typedef unsigned short us;

    // 1) split-convert activations + weights (once)
    convert_split_kernel<<<1024, 256>>>(query, (us*)cqh, (us*)cql, M_*D_/4);
    convert_split_kernel<<<1024, 256>>>(key_,  (us*)ckh, (us*)ckl, M_*D_/4);
    convert_split_kernel<<<1024, 256>>>(value, (us*)cvh, (us*)cvl, M_*D_/4);
    convert_split_kernel<<<256, 256>>>(Wq, (us*)wqh, (us*)wql, D_*D_/4);
    convert_split_kernel<<<256, 256>>>(Wk, (us*)wkh, (us*)wkl, D_*D_/4);
    convert_split_kernel<<<256, 256>>>(Wv, (us*)wvh, (us*)wvl, D_*D_/4);
    convert_split_kernel<<<256, 256>>>(Wo, (us*)woh, (us*)wol, D_*D_/4);

    // 2) projections (tensor cores), writing bf16 h/l in attention layouts
    const dim3 ggrid(D_/128, M_/128);   // (8, 64)
    gemm_bf16_kernel<0><<<ggrid, 256, GSMEM>>>(
        (const us*)cqh, (const us*)cql, (const us*)wqh, (const us*)wql,
        bq, nullptr, (us*)pqh, (us*)pql);
    gemm_bf16_kernel<0><<<ggrid, 256, GSMEM>>>(
        (const us*)ckh, (const us*)ckl, (const us*)wkh, (const us*)wkl,
        bk, nullptr, (us*)pkh, (us*)pkl);
    gemm_bf16_kernel<1><<<ggrid, 256, GSMEM>>>(
        (const us*)cvh, (const us*)cvl, (const us*)wvh, (const us*)wvl,
        bv, nullptr, (us*)pvth, (us*)pvtl);

    // 3) flash attention (tensor cores)
    flash_mma_kernel<<<dim3(S_/128, B_*H_), 256, F_SMEM>>>(mask);

    // 4) output projection -> fp32 out
    gemm_bf16_kernel<2><<<ggrid, 256, GSMEM>>>(
        (const us*)xh, (const us*)xl, (const us*)woh, (const us*)wol,
        bo, out, nullptr, nullptr);
}

// round 8
// speedup vs baseline: 2.1817x; 1.0711x over previous
#include <cuda_runtime.h>
#include <cuda_bf16.h>
#include <cstdint>

#define B_  4
#define S_  2048
#define D_  1024
#define H_  16
#define DK_ 64
#define M_  (B_*S_)

// ---------------------------------------------------------------------------
// Scratch (bf16 bit-patterns held in ushort arrays; no allocation APIs)
// ---------------------------------------------------------------------------
__device__ unsigned short c_qh[M_*D_], c_ql[M_*D_];
__device__ unsigned short c_kh[M_*D_], c_kl[M_*D_];
__device__ unsigned short c_vh[M_*D_], c_vl[M_*D_];
__device__ unsigned short w_qh[D_*D_], w_ql[D_*D_];
__device__ unsigned short w_kh[D_*D_], w_kl[D_*D_];
__device__ unsigned short w_vh[D_*D_], w_vl[D_*D_];
__device__ unsigned short w_oh[D_*D_], w_ol[D_*D_];
__device__ unsigned short p_qh[M_*D_], p_ql[M_*D_];   // Q proj, [bh][s][dk]
__device__ unsigned short p_kh[M_*D_], p_kl[M_*D_];   // K proj, [bh][s][dk]
__device__ unsigned short p_vth[M_*D_], p_vtl[M_*D_]; // V proj, [bh][dk][s]
__device__ unsigned short x_h[M_*D_], x_l[M_*D_];     // attn out, [b][s][d]

// ---------------------------------------------------------------------------
// Helpers (arch-portable PTX: ldmatrix + mma.sync + cp.async)
// ---------------------------------------------------------------------------
__device__ __forceinline__ uint32_t smem_u32(const void* p) {
    uint32_t a;
    asm("{ .reg .u64 t; cvta.to.shared.u64 t, %1; cvt.u32.u64 %0, t; }"
        : "=r"(a) : "l"(p));
    return a;
}
__device__ __forceinline__ void ldsm_x4(uint32_t* r, uint32_t addr) {
    asm volatile("ldmatrix.sync.aligned.m8n8.x4.shared.b16 {%0,%1,%2,%3}, [%4];"
                 : "=r"(r[0]), "=r"(r[1]), "=r"(r[2]), "=r"(r[3]) : "r"(addr));
}
__device__ __forceinline__ void mma_bf16(float* c, const uint32_t* a,
                                         const uint32_t* b) {
    asm volatile(
        "mma.sync.aligned.m16n8k16.row.col.f32.bf16.bf16.f32 "
        "{%0,%1,%2,%3}, {%4,%5,%6,%7}, {%8,%9}, {%0,%1,%2,%3};"
        : "+f"(c[0]), "+f"(c[1]), "+f"(c[2]), "+f"(c[3])
        : "r"(a[0]), "r"(a[1]), "r"(a[2]), "r"(a[3]), "r"(b[0]), "r"(b[1]));
}
__device__ __forceinline__ void cp16(uint32_t dst, const void* src) {
    asm volatile("cp.async.cg.shared.global [%0], [%1], 16;"
                 :: "r"(dst), "l"(src) : "memory");
}
#define CP_COMMIT()  asm volatile("cp.async.commit_group;" ::: "memory")
#define CP_WAIT(n)   asm volatile("cp.async.wait_group %0;" :: "n"(n) : "memory")

__device__ __forceinline__ void split_bf16(float x, uint16_t& h, uint16_t& l) {
    __nv_bfloat16 hb = __float2bfloat16_rn(x);
    float r = x - __bfloat162float(hb);
    __nv_bfloat16 lb = __float2bfloat16_rn(r);
    h = __bfloat16_as_ushort(hb);
    l = __bfloat16_as_ushort(lb);
}
__device__ __forceinline__ void split_pack2(float x, float y,
                                            uint32_t& hp, uint32_t& lp) {
    uint16_t hx, lx, hy, ly;
    split_bf16(x, hx, lx);
    split_bf16(y, hy, ly);
    hp = (uint32_t)hx | ((uint32_t)hy << 16);
    lp = (uint32_t)lx | ((uint32_t)ly << 16);
}

// ---------------------------------------------------------------------------
// Convert: fp32 -> (hi, lo) bf16 arrays
// ---------------------------------------------------------------------------
__global__ void convert_split_kernel(const float* __restrict__ in,
                                     unsigned short* __restrict__ hi,
                                     unsigned short* __restrict__ lo, int n4)
{
    const int stride = gridDim.x * blockDim.x;
    for (int i = blockIdx.x * blockDim.x + threadIdx.x; i < n4; i += stride) {
        float4 v = ((const float4*)in)[i];
        uint32_t h0, l0, h1, l1;
        split_pack2(v.x, v.y, h0, l0);
        split_pack2(v.z, v.w, h1, l1);
        ((uint2*)hi)[i] = make_uint2(h0, h1);
        ((uint2*)lo)[i] = make_uint2(l0, l1);
    }
}

// ---------------------------------------------------------------------------
// bf16-split (3-term) tensor-core GEMM, cp.async 2-stage pipeline:
//   C[m][n] = sum_k A[m][k] * W[n][k] + bias[n]
// CTA 128x128, BK=32, 8 warps (2x4), warp tile 64x32.
// OUTMODE 0: bf16 h/l head layout [bh][s][dk]
// OUTMODE 1: bf16 h/l transposed head layout [bh][dk][s]
// OUTMODE 2: fp32 natural [m][n]
// ---------------------------------------------------------------------------
#define GROWB  80                        // row bytes (32 bf16 + 8 pad)
#define GARR   (128 * GROWB)             // 10240 B
#define GSTAGE (4 * GARR)
#define GSMEM  (2 * GSTAGE)              // 81920 B

template<int OUTMODE>
__global__ __launch_bounds__(256)
void gemm_bf16_kernel(const unsigned short* __restrict__ Ah,
                      const unsigned short* __restrict__ Al,
                      const unsigned short* __restrict__ Wh,
                      const unsigned short* __restrict__ Wl,
                      const float* __restrict__ bias,
                      float* __restrict__ out32,
                      unsigned short* __restrict__ outh,
                      unsigned short* __restrict__ outl)
{
    extern __shared__ char dsm[];
    const uint32_t sbase = smem_u32(dsm);

    const int tid  = threadIdx.x;
    const int lane = tid & 31;
    const int warp = tid >> 5;
    const int wm   = warp >> 2;
    const int wn   = warp & 3;
    const int bm   = blockIdx.y;
    const int bn   = blockIdx.x;

    const int arow = (lane & 7) + ((lane >> 3) & 1) * 8;
    const int acol = ((lane >> 4) & 1) * 8;
    const int brow = (lane & 7) + ((lane >> 4) & 1) * 8;
    const int bcol = ((lane >> 3) & 1) * 8;

    const int r    = tid >> 1;
    const int half = tid & 1;
    const unsigned short* Ap  = Ah + (size_t)(bm * 128 + r) * D_ + half * 16;
    const unsigned short* Alp = Al + (size_t)(bm * 128 + r) * D_ + half * 16;
    const unsigned short* Wp  = Wh + (size_t)(bn * 128 + r) * D_ + half * 16;
    const unsigned short* Wlp = Wl + (size_t)(bn * 128 + r) * D_ + half * 16;
    const uint32_t st_off = (uint32_t)(r * GROWB + half * 32);

    float acc[4][4][4];
#pragma unroll
    for (int i = 0; i < 4; i++)
#pragma unroll
        for (int j = 0; j < 4; j++)
#pragma unroll
            for (int e = 0; e < 4; e++) acc[i][j][e] = 0.f;

    auto load_chunk = [&](int c, uint32_t stg) {
        const int kt = c * 32;
        const uint32_t a0 = stg + st_off;
        cp16(a0,              Ap + kt);
        cp16(a0 + 16,         Ap + kt + 8);
        cp16(a0 + GARR,       Alp + kt);
        cp16(a0 + GARR + 16,  Alp + kt + 8);
        cp16(a0 + 2*GARR,      Wp + kt);
        cp16(a0 + 2*GARR + 16, Wp + kt + 8);
        cp16(a0 + 3*GARR,      Wlp + kt);
        cp16(a0 + 3*GARR + 16, Wlp + kt + 8);
    };

    load_chunk(0, sbase);
    CP_COMMIT();

    const uint32_t aoff0 = (uint32_t)((wm * 64 + arow) * GROWB + acol * 2);
    const uint32_t boff0 = (uint32_t)((wn * 32 + brow) * GROWB + bcol * 2);

    for (int c = 0; c < 32; c++) {
        const uint32_t stg = sbase + (uint32_t)(c & 1) * GSTAGE;
        if (c < 31) {
            load_chunk(c + 1, sbase + (uint32_t)((c + 1) & 1) * GSTAGE);
            CP_COMMIT();
            CP_WAIT(1);
        } else {
            CP_WAIT(0);
        }
        __syncthreads();

#pragma unroll
        for (int ks = 0; ks < 2; ks++) {
            const uint32_t kb = (uint32_t)(ks * 32);
            uint32_t aH[4][4], aL[4][4];
#pragma unroll
            for (int mt = 0; mt < 4; mt++) {
                const uint32_t ao = stg + aoff0 + (uint32_t)(mt*16*GROWB) + kb;
                ldsm_x4(aH[mt], ao);
                ldsm_x4(aL[mt], ao + GARR);
            }
            uint32_t bH[2][4], bL[2][4];
#pragma unroll
            for (int ng = 0; ng < 2; ng++) {
                const uint32_t bo = stg + 2*GARR + boff0
                                  + (uint32_t)(ng*16*GROWB) + kb;
                ldsm_x4(bH[ng], bo);
                ldsm_x4(bL[ng], bo + GARR);
            }
#pragma unroll
            for (int mt = 0; mt < 4; mt++) {
#pragma unroll
                for (int nt = 0; nt < 4; nt++) {
                    const uint32_t* bh = &bH[nt >> 1][(nt & 1) * 2];
                    const uint32_t* bl = &bL[nt >> 1][(nt & 1) * 2];
                    mma_bf16(acc[mt][nt], aH[mt], bh);
                    mma_bf16(acc[mt][nt], aH[mt], bl);
                    mma_bf16(acc[mt][nt], aL[mt], bh);
                }
            }
        }
        __syncthreads();
    }

    // Epilogue
    const int rl = lane >> 2;
    const int cl = 2 * (lane & 3);
#pragma unroll
    for (int mt = 0; mt < 4; mt++) {
#pragma unroll
        for (int nt = 0; nt < 4; nt++) {
            const int n = bn * 128 + wn * 32 + nt * 8 + cl;
            const float b0 = bias[n], b1 = bias[n + 1];
#pragma unroll
            for (int hf = 0; hf < 2; hf++) {
                const int m = bm * 128 + wm * 64 + mt * 16 + rl + hf * 8;
                const float vx = acc[mt][nt][hf * 2 + 0] + b0;
                const float vy = acc[mt][nt][hf * 2 + 1] + b1;
                const int h  = n >> 6;
                const int dk = n & 63;
                const int bb = m >> 11;
                const int ss = m & 2047;
                if (OUTMODE == 2) {
                    *(float2*)(out32 + (size_t)m * D_ + n) = make_float2(vx, vy);
                } else if (OUTMODE == 0) {
                    const size_t idx = ((size_t)((bb*H_ + h)*S_ + ss))*DK_ + dk;
                    uint32_t hp, lp;
                    split_pack2(vx, vy, hp, lp);
                    *(uint32_t*)(outh + idx) = hp;
                    *(uint32_t*)(outl + idx) = lp;
                } else {
                    const size_t idx = ((size_t)((bb*H_ + h)*DK_ + dk))*S_ + ss;
                    uint16_t hx, lx, hy, ly;
                    split_bf16(vx, hx, lx);
                    split_bf16(vy, hy, ly);
                    outh[idx] = hx;        outl[idx] = lx;
                    outh[idx + S_] = hy;   outl[idx + S_] = ly;
                }
            }
        }
    }
}

// ---------------------------------------------------------------------------
// Tensor-core flash attention, cp.async 2-stage K/V pipeline, register P.
// Grid (qb=16, bh=64), 256 threads (8 warps), warp owns 16 q-rows.
// S C-fragment == PV A-fragment layout -> P never touches smem.
// ---------------------------------------------------------------------------
#define QKROWB 144                       // 72 bf16 row stride (Q/K tiles)
#define VTROWB 272                       // 136 bf16 row stride (Vt tile)
#define QK_BYTES (128 * QKROWB)          // 18432
#define VT_BYTES (64 * VTROWB)           // 17408
#define FQ_H  0
#define FQ_L  QK_BYTES
#define FSTG0 (2 * QK_BYTES)             // 36864
#define SG_KH 0
#define SG_KL QK_BYTES
#define SG_VH (2 * QK_BYTES)
#define SG_VL (2 * QK_BYTES + VT_BYTES)
#define STG_B (2 * QK_BYTES + 2 * VT_BYTES)   // 71680
#define F_SMEM (FSTG0 + 2 * STG_B)            // 180224

__global__ __launch_bounds__(256, 1)
void flash_mma_kernel(const int* __restrict__ mask)
{
    extern __shared__ char dsm[];
    const uint32_t sb = smem_u32(dsm);

    const int tid  = threadIdx.x;
    const int lane = tid & 31;
    const int warp = tid >> 5;
    const int qb   = blockIdx.x;
    const int bh   = blockIdx.y;
    const int q0   = qb * 128;

    const int arow = (lane & 7) + ((lane >> 3) & 1) * 8;
    const int acol = ((lane >> 4) & 1) * 8;
    const int brow = (lane & 7) + ((lane >> 4) & 1) * 8;
    const int bcol = ((lane >> 3) & 1) * 8;
    const int ln2  = lane & 3;
    const int r0   = warp * 16 + (lane >> 2);

    const unsigned short* Qhp = p_qh + (size_t)bh * S_ * DK_;
    const unsigned short* Qlp = p_ql + (size_t)bh * S_ * DK_;
    const unsigned short* Khp = p_kh + (size_t)bh * S_ * DK_;
    const unsigned short* Klp = p_kl + (size_t)bh * S_ * DK_;
    const unsigned short* Vhp = p_vth + (size_t)bh * DK_ * S_;
    const unsigned short* Vlp = p_vtl + (size_t)bh * DK_ * S_;

    const int row  = tid >> 1, seg  = tid & 1;
    const int vrow = tid >> 2, vseg = tid & 3;

    auto load_kv = [&](int t0, int buf) {
        const uint32_t st = sb + FSTG0 + (uint32_t)buf * STG_B;
        const size_t g = (size_t)(t0 + row) * DK_ + seg * 32;
        const uint32_t s = st + row * QKROWB + seg * 64;
#pragma unroll
        for (int i = 0; i < 4; i++) {
            cp16(s + SG_KH + i*16, Khp + g + i*8);
            cp16(s + SG_KL + i*16, Klp + g + i*8);
        }
        const size_t gv = (size_t)vrow * S_ + t0 + vseg * 32;
        const uint32_t sv = st + vrow * VTROWB + vseg * 64;
#pragma unroll
        for (int i = 0; i < 4; i++) {
            cp16(sv + SG_VH + i*16, Vhp + gv + i*8);
            cp16(sv + SG_VL + i*16, Vlp + gv + i*8);
        }
    };

    // Q tile (once) + KV tile 0, one commit group
    {
        const size_t g = (size_t)(q0 + row) * DK_ + seg * 32;
        const uint32_t s = sb + row * QKROWB + seg * 64;
#pragma unroll
        for (int i = 0; i < 4; i++) {
            cp16(s + FQ_H + i*16, Qhp + g + i*8);
            cp16(s + FQ_L + i*16, Qlp + g + i*8);
        }
    }
    load_kv(0, 0);
    CP_COMMIT();

    float m0 = -1e30f, m1 = -1e30f, l0 = 0.f, l1 = 0.f;
    float oacc[8][4];
#pragma unroll
    for (int j = 0; j < 8; j++)
#pragma unroll
        for (int e = 0; e < 4; e++) oacc[j][e] = 0.f;

    for (int it = 0; it < 16; it++) {
        const int buf = it & 1;
        if (it < 15) {
            load_kv((it + 1) * 128, 1 - buf);
            CP_COMMIT();
            CP_WAIT(1);
        } else {
            CP_WAIT(0);
        }
        __syncthreads();
        const uint32_t st = sb + FSTG0 + (uint32_t)buf * STG_B;
        const int t0 = it * 128;

        // ---- S = Q K^T
        float sacc[16][4];
#pragma unroll
        for (int j = 0; j < 16; j++)
#pragma unroll
            for (int e = 0; e < 4; e++) sacc[j][e] = 0.f;

#pragma unroll
        for (int ks = 0; ks < 4; ks++) {
            const uint32_t kb = (uint32_t)(ks * 32);
            uint32_t aH[4], aL[4];
            const uint32_t ao = sb + (warp*16 + arow) * QKROWB + acol*2 + kb;
            ldsm_x4(aH, ao + FQ_H);
            ldsm_x4(aL, ao + FQ_L);
#pragma unroll
            for (int j16 = 0; j16 < 8; j16++) {
                uint32_t bH[4], bL[4];
                const uint32_t bo = st + (j16*16 + brow) * QKROWB + bcol*2 + kb;
                ldsm_x4(bH, bo + SG_KH);
                ldsm_x4(bL, bo + SG_KL);
#pragma unroll
                for (int hf = 0; hf < 2; hf++) {
                    float* a2 = sacc[j16*2 + hf];
                    mma_bf16(a2, aH, &bH[hf*2]);
                    mma_bf16(a2, aH, &bL[hf*2]);
                    mma_bf16(a2, aL, &bH[hf*2]);
                }
            }
        }

        // ---- mask + online softmax; P stays in sacc registers
#pragma unroll
        for (int p = 0; p < 2; p++) {
            const int r  = r0 + p * 8;
            const int eb = p * 2;
            const int* mrow = mask + (size_t)(q0 + r) * S_ + t0 + 2*ln2;

            float mx = -1e30f;
#pragma unroll
            for (int j = 0; j < 16; j++) {
                const int2 mv = *(const int2*)(mrow + j * 8);
                float v0 = sacc[j][eb+0] * 0.125f; if (mv.x == 0) v0 = -1e9f;
                float v1 = sacc[j][eb+1] * 0.125f; if (mv.y == 0) v1 = -1e9f;
                sacc[j][eb+0] = v0;
                sacc[j][eb+1] = v1;
                mx = fmaxf(mx, fmaxf(v0, v1));
            }
            mx = fmaxf(mx, __shfl_xor_sync(0xffffffffu, mx, 1));
            mx = fmaxf(mx, __shfl_xor_sync(0xffffffffu, mx, 2));

            const float mp   = (p == 0) ? m0 : m1;
            const float mnew = fmaxf(mp, mx);
            const float corr = __expf(mp - mnew);
            float sum = 0.f;
#pragma unroll
            for (int j = 0; j < 16; j++) {
                const float p0 = __expf(sacc[j][eb+0] - mnew);
                const float p1 = __expf(sacc[j][eb+1] - mnew);
                sacc[j][eb+0] = p0;
                sacc[j][eb+1] = p1;
                sum += p0 + p1;
            }
            sum += __shfl_xor_sync(0xffffffffu, sum, 1);
            sum += __shfl_xor_sync(0xffffffffu, sum, 2);

            if (p == 0) { l0 = l0 * corr + sum; m0 = mnew; }
            else        { l1 = l1 * corr + sum; m1 = mnew; }
#pragma unroll
            for (int j = 0; j < 8; j++) {
                oacc[j][eb+0] *= corr;
                oacc[j][eb+1] *= corr;
            }
        }

        // ---- O += P V : A-fragments of P built in registers from sacc
#pragma unroll
        for (int ks = 0; ks < 8; ks++) {
            uint32_t aH[4], aL[4];
            split_pack2(sacc[2*ks  ][0], sacc[2*ks  ][1], aH[0], aL[0]);
            split_pack2(sacc[2*ks  ][2], sacc[2*ks  ][3], aH[1], aL[1]);
            split_pack2(sacc[2*ks+1][0], sacc[2*ks+1][1], aH[2], aL[2]);
            split_pack2(sacc[2*ks+1][2], sacc[2*ks+1][3], aH[3], aL[3]);
            const uint32_t kb = (uint32_t)(ks * 32);
#pragma unroll
            for (int j16 = 0; j16 < 4; j16++) {
                uint32_t bH[4], bL[4];
                const uint32_t bo = st + (j16*16 + brow) * VTROWB + bcol*2 + kb;
                ldsm_x4(bH, bo + SG_VH);
                ldsm_x4(bL, bo + SG_VL);
#pragma unroll
                for (int hf = 0; hf < 2; hf++) {
                    float* a2 = oacc[j16*2 + hf];
                    mma_bf16(a2, aH, &bH[hf*2]);
                    mma_bf16(a2, aH, &bL[hf*2]);
                    mma_bf16(a2, aL, &bH[hf*2]);
                }
            }
        }
        __syncthreads();
    }

    // ---- epilogue: X[b][s][h*64+dk] bf16 hi/lo
    const int bb = bh >> 4, hh = bh & 15;
#pragma unroll
    for (int p = 0; p < 2; p++) {
        const int r   = r0 + p * 8;
        const int eb  = p * 2;
        const float inv = 1.f / ((p == 0) ? l0 : l1);
        const size_t base = ((size_t)(bb * S_ + q0 + r)) * D_ + hh * DK_ + 2*ln2;
#pragma unroll
        for (int j = 0; j < 8; j++) {
            uint32_t hp, lp;
            split_pack2(oacc[j][eb+0] * inv, oacc[j][eb+1] * inv, hp, lp);
            *(uint32_t*)(x_h + base + j*8) = hp;
            *(uint32_t*)(x_l + base + j*8) = lp;
        }
    }
}

// ---------------------------------------------------------------------------
extern "C" void kernel_launch(void* const* d_in, const int* in_sizes, int n_in,
                              void* d_out, int out_size)
{
    (void)in_sizes; (void)n_in; (void)out_size;
    const float* query = (const float*)d_in[0];
    const float* key_  = (const float*)d_in[1];
    const float* value = (const float*)d_in[2];
    const int*   mask  = (const int*)  d_in[3];
    const float* Wq    = (const float*)d_in[4];
    const float* bq    = (const float*)d_in[5];
    const float* Wk    = (const float*)d_in[6];
    const float* bk    = (const float*)d_in[7];
    const float* Wv    = (const float*)d_in[8];
    const float* bv    = (const float*)d_in[9];
    const float* Wo    = (const float*)d_in[10];
    const float* bo    = (const float*)d_in[11];
    float* out = (float*)d_out;

    cudaFuncSetAttribute(flash_mma_kernel,
                         cudaFuncAttributeMaxDynamicSharedMemorySize, F_SMEM);
    cudaFuncSetAttribute(gemm_bf16_kernel<0>,
                         cudaFuncAttributeMaxDynamicSharedMemorySize, GSMEM);
    cudaFuncSetAttribute(gemm_bf16_kernel<1>,
                         cudaFuncAttributeMaxDynamicSharedMemorySize, GSMEM);
    cudaFuncSetAttribute(gemm_bf16_kernel<2>,
                         cudaFuncAttributeMaxDynamicSharedMemorySize, GSMEM);

    void *cqh,*cql,*ckh,*ckl,*cvh,*cvl;
    void *wqh,*wql,*wkh,*wkl,*wvh,*wvl,*woh,*wol;
    void *pqh,*pql,*pkh,*pkl,*pvth,*pvtl,*xh,*xl;
    cudaGetSymbolAddress(&cqh, c_qh); cudaGetSymbolAddress(&cql, c_ql);
    cudaGetSymbolAddress(&ckh, c_kh); cudaGetSymbolAddress(&ckl, c_kl);
    cudaGetSymbolAddress(&cvh, c_vh); cudaGetSymbolAddress(&cvl, c_vl);
    cudaGetSymbolAddress(&wqh, w_qh); cudaGetSymbolAddress(&wql, w_ql);
    cudaGetSymbolAddress(&wkh, w_kh); cudaGetSymbolAddress(&wkl, w_kl);
    cudaGetSymbolAddress(&wvh, w_vh); cudaGetSymbolAddress(&wvl, w_vl);
    cudaGetSymbolAddress(&woh, w_oh); cudaGetSymbolAddress(&wol, w_ol);
    cudaGetSymbolAddress(&pqh, p_qh); cudaGetSymbolAddress(&pql, p_ql);
    cudaGetSymbolAddress(&pkh, p_kh); cudaGetSymbolAddress(&pkl, p_kl);
    cudaGetSymbolAddress(&pvth, p_vth); cudaGetSymbolAddress(&pvtl, p_vtl);
    cudaGetSymbolAddress(&xh, x_h); cudaGetSymbolAddress(&xl, x_l);

    typedef unsigned short us;

    convert_split_kernel<<<1024, 256>>>(query, (us*)cqh, (us*)cql, M_*D_/4);
    convert_split_kernel<<<1024, 256>>>(key_,  (us*)ckh, (us*)ckl, M_*D_/4);
    convert_split_kernel<<<1024, 256>>>(value, (us*)cvh, (us*)cvl, M_*D_/4);
    convert_split_kernel<<<512, 256>>>(Wq, (us*)wqh, (us*)wql, D_*D_/4);
    convert_split_kernel<<<512, 256>>>(Wk, (us*)wkh, (us*)wkl, D_*D_/4);
    convert_split_kernel<<<512, 256>>>(Wv, (us*)wvh, (us*)wvl, D_*D_/4);
    convert_split_kernel<<<512, 256>>>(Wo, (us*)woh, (us*)wol, D_*D_/4);

    const dim3 ggrid(D_/128, M_/128);   // (8, 64)
    gemm_bf16_kernel<0><<<ggrid, 256, GSMEM>>>(
        (const us*)cqh, (const us*)cql, (const us*)wqh, (const us*)wql,
        bq, nullptr, (us*)pqh, (us*)pql);
    gemm_bf16_kernel<0><<<ggrid, 256, GSMEM>>>(
        (const us*)ckh, (const us*)ckl, (const us*)wkh, (const us*)wkl,
        bk, nullptr, (us*)pkh, (us*)pkl);
    gemm_bf16_kernel<1><<<ggrid, 256, GSMEM>>>(
        (const us*)cvh, (const us*)cvl, (const us*)wvh, (const us*)wvl,
        bv, nullptr, (us*)pvth, (us*)pvtl);

    flash_mma_kernel<<<dim3(S_/128, B_*H_), 256, F_SMEM>>>(mask);

    gemm_bf16_kernel<2><<<ggrid, 256, GSMEM>>>(
        (const us*)xh, (const us*)xl, (const us*)woh, (const us*)wol,
        bo, out, nullptr, nullptr);
}

// round 9
// speedup vs baseline: 2.4972x; 1.1446x over previous
#include <cuda_runtime.h>
#include <cuda_fp16.h>
#include <cstdint>

#define B_  4
#define S_  2048
#define D_  1024
#define H_  16
#define DK_ 64
#define M_  (B_*S_)

// ---------------------------------------------------------------------------
// Scratch (fp16 bit-patterns in ushort arrays; no allocation APIs)
// ---------------------------------------------------------------------------
__device__ unsigned short c_qh[M_*D_], c_ql[M_*D_];
__device__ unsigned short c_kh[M_*D_], c_kl[M_*D_];
__device__ unsigned short c_vh[M_*D_], c_vl[M_*D_];
__device__ unsigned short w_qh[D_*D_], w_ql[D_*D_];
__device__ unsigned short w_kh[D_*D_], w_kl[D_*D_];
__device__ unsigned short w_vh[D_*D_], w_vl[D_*D_];
__device__ unsigned short w_oh[D_*D_], w_ol[D_*D_];
__device__ unsigned short p_qh[M_*D_], p_ql[M_*D_];   // Q proj, [bh][s][dk]
__device__ unsigned short p_kh[M_*D_], p_kl[M_*D_];   // K proj, [bh][s][dk]
__device__ unsigned short p_vth[M_*D_], p_vtl[M_*D_]; // V proj, [bh][dk][s]
__device__ unsigned short x_h[M_*D_], x_l[M_*D_];     // attn out, [b][s][d]
__device__ unsigned int   m_bits[S_*S_/32];           // mask bitmask

// ---------------------------------------------------------------------------
// Helpers (arch-portable PTX: ldmatrix + mma.sync + cp.async)
// ---------------------------------------------------------------------------
__device__ __forceinline__ uint32_t smem_u32(const void* p) {
    uint32_t a;
    asm("{ .reg .u64 t; cvta.to.shared.u64 t, %1; cvt.u32.u64 %0, t; }"
        : "=r"(a) : "l"(p));
    return a;
}
__device__ __forceinline__ void ldsm_x4(uint32_t* r, uint32_t addr) {
    asm volatile("ldmatrix.sync.aligned.m8n8.x4.shared.b16 {%0,%1,%2,%3}, [%4];"
                 : "=r"(r[0]), "=r"(r[1]), "=r"(r[2]), "=r"(r[3]) : "r"(addr));
}
__device__ __forceinline__ void mma_f16(float* c, const uint32_t* a,
                                        const uint32_t* b) {
    asm volatile(
        "mma.sync.aligned.m16n8k16.row.col.f32.f16.f16.f32 "
        "{%0,%1,%2,%3}, {%4,%5,%6,%7}, {%8,%9}, {%0,%1,%2,%3};"
        : "+f"(c[0]), "+f"(c[1]), "+f"(c[2]), "+f"(c[3])
        : "r"(a[0]), "r"(a[1]), "r"(a[2]), "r"(a[3]), "r"(b[0]), "r"(b[1]));
}
__device__ __forceinline__ void cp16(uint32_t dst, const void* src) {
    asm volatile("cp.async.cg.shared.global [%0], [%1], 16;"
                 :: "r"(dst), "l"(src) : "memory");
}
#define CP_COMMIT()  asm volatile("cp.async.commit_group;" ::: "memory")
#define CP_WAIT(n)   asm volatile("cp.async.wait_group %0;" :: "n"(n) : "memory")

__device__ __forceinline__ void split_f16(float x, uint16_t& h, uint16_t& l) {
    __half hb = __float2half_rn(x);
    float r = x - __half2float(hb);
    __half lb = __float2half_rn(r);
    h = __half_as_ushort(hb);
    l = __half_as_ushort(lb);
}
__device__ __forceinline__ void split_pack2(float x, float y,
                                            uint32_t& hp, uint32_t& lp) {
    uint16_t hx, lx, hy, ly;
    split_f16(x, hx, lx);
    split_f16(y, hy, ly);
    hp = (uint32_t)hx | ((uint32_t)hy << 16);
    lp = (uint32_t)lx | ((uint32_t)ly << 16);
}
__device__ __forceinline__ uint32_t pack_h2(float lo, float hi) {
    __half2 h = __floats2half2_rn(lo, hi);
    return *(uint32_t*)&h;
}

// ---------------------------------------------------------------------------
// Fused convert: 7 tensors fp32 -> (hi, lo) fp16 in one launch
// ---------------------------------------------------------------------------
struct CvtArgs {
    const float*    in[7];
    unsigned short* hi[7];
    unsigned short* lo[7];
};

__global__ void convert_all_kernel(CvtArgs args, int n4_act, int n4_w)
{
    const int z  = blockIdx.y;
    const int n4 = (z < 3) ? n4_act : n4_w;
    const float* in = args.in[z];
    unsigned short* hi = args.hi[z];
    unsigned short* lo = args.lo[z];
    const int stride = gridDim.x * blockDim.x;
    for (int i = blockIdx.x * blockDim.x + threadIdx.x; i < n4; i += stride) {
        float4 v = ((const float4*)in)[i];
        uint32_t h0, l0, h1, l1;
        split_pack2(v.x, v.y, h0, l0);
        split_pack2(v.z, v.w, h1, l1);
        ((uint2*)hi)[i] = make_uint2(h0, h1);
        ((uint2*)lo)[i] = make_uint2(l0, l1);
    }
}

// ---------------------------------------------------------------------------
// Mask -> bitmask (1 bit per entry). Thread builds one 32-bit word.
// ---------------------------------------------------------------------------
__global__ void mask_bits_kernel(const int* __restrict__ mask)
{
    const int w = blockIdx.x * blockDim.x + threadIdx.x;   // word index
    if (w >= S_*S_/32) return;
    const int4* p = (const int4*)(mask + (size_t)w * 32);
    uint32_t bits = 0;
#pragma unroll
    for (int i = 0; i < 8; i++) {
        int4 v = p[i];
        bits |= (uint32_t)(v.x != 0) << (i*4 + 0);
        bits |= (uint32_t)(v.y != 0) << (i*4 + 1);
        bits |= (uint32_t)(v.z != 0) << (i*4 + 2);
        bits |= (uint32_t)(v.w != 0) << (i*4 + 3);
    }
    m_bits[w] = bits;
}

// ---------------------------------------------------------------------------
// fp16-split (3-term) tensor-core GEMM, cp.async 2-stage pipeline:
//   C[m][n] = sum_k A[m][k] * W[n][k] + bias[n]
// OUTMODE 0: fp16 h/l head layout [bh][s][dk]
// OUTMODE 1: fp16 h/l transposed head layout [bh][dk][s]
// OUTMODE 2: fp32 natural [m][n]
// ---------------------------------------------------------------------------
#define GROWB  80
#define GARR   (128 * GROWB)
#define GSTAGE (4 * GARR)
#define GSMEM  (2 * GSTAGE)              // 81920 B

template<int OUTMODE>
__global__ __launch_bounds__(256)
void gemm_f16_kernel(const unsigned short* __restrict__ Ah,
                     const unsigned short* __restrict__ Al,
                     const unsigned short* __restrict__ Wh,
                     const unsigned short* __restrict__ Wl,
                     const float* __restrict__ bias,
                     float* __restrict__ out32,
                     unsigned short* __restrict__ outh,
                     unsigned short* __restrict__ outl)
{
    extern __shared__ char dsm[];
    const uint32_t sbase = smem_u32(dsm);

    const int tid  = threadIdx.x;
    const int lane = tid & 31;
    const int warp = tid >> 5;
    const int wm   = warp >> 2;
    const int wn   = warp & 3;
    const int bm   = blockIdx.y;
    const int bn   = blockIdx.x;

    const int arow = (lane & 7) + ((lane >> 3) & 1) * 8;
    const int acol = ((lane >> 4) & 1) * 8;
    const int brow = (lane & 7) + ((lane >> 4) & 1) * 8;
    const int bcol = ((lane >> 3) & 1) * 8;

    const int r    = tid >> 1;
    const int half = tid & 1;
    const unsigned short* Ap  = Ah + (size_t)(bm * 128 + r) * D_ + half * 16;
    const unsigned short* Alp = Al + (size_t)(bm * 128 + r) * D_ + half * 16;
    const unsigned short* Wp  = Wh + (size_t)(bn * 128 + r) * D_ + half * 16;
    const unsigned short* Wlp = Wl + (size_t)(bn * 128 + r) * D_ + half * 16;
    const uint32_t st_off = (uint32_t)(r * GROWB + half * 32);

    float acc[4][4][4];
#pragma unroll
    for (int i = 0; i < 4; i++)
#pragma unroll
        for (int j = 0; j < 4; j++)
#pragma unroll
            for (int e = 0; e < 4; e++) acc[i][j][e] = 0.f;

    auto load_chunk = [&](int c, uint32_t stg) {
        const int kt = c * 32;
        const uint32_t a0 = stg + st_off;
        cp16(a0,              Ap + kt);
        cp16(a0 + 16,         Ap + kt + 8);
        cp16(a0 + GARR,       Alp + kt);
        cp16(a0 + GARR + 16,  Alp + kt + 8);
        cp16(a0 + 2*GARR,      Wp + kt);
        cp16(a0 + 2*GARR + 16, Wp + kt + 8);
        cp16(a0 + 3*GARR,      Wlp + kt);
        cp16(a0 + 3*GARR + 16, Wlp + kt + 8);
    };

    load_chunk(0, sbase);
    CP_COMMIT();

    const uint32_t aoff0 = (uint32_t)((wm * 64 + arow) * GROWB + acol * 2);
    const uint32_t boff0 = (uint32_t)((wn * 32 + brow) * GROWB + bcol * 2);

    for (int c = 0; c < 32; c++) {
        const uint32_t stg = sbase + (uint32_t)(c & 1) * GSTAGE;
        if (c < 31) {
            load_chunk(c + 1, sbase + (uint32_t)((c + 1) & 1) * GSTAGE);
            CP_COMMIT();
            CP_WAIT(1);
        } else {
            CP_WAIT(0);
        }
        __syncthreads();

#pragma unroll
        for (int ks = 0; ks < 2; ks++) {
            const uint32_t kb = (uint32_t)(ks * 32);
            uint32_t aH[4][4], aL[4][4];
#pragma unroll
            for (int mt = 0; mt < 4; mt++) {
                const uint32_t ao = stg + aoff0 + (uint32_t)(mt*16*GROWB) + kb;
                ldsm_x4(aH[mt], ao);
                ldsm_x4(aL[mt], ao + GARR);
            }
            uint32_t bH[2][4], bL[2][4];
#pragma unroll
            for (int ng = 0; ng < 2; ng++) {
                const uint32_t bo = stg + 2*GARR + boff0
                                  + (uint32_t)(ng*16*GROWB) + kb;
                ldsm_x4(bH[ng], bo);
                ldsm_x4(bL[ng], bo + GARR);
            }
#pragma unroll
            for (int mt = 0; mt < 4; mt++) {
#pragma unroll
                for (int nt = 0; nt < 4; nt++) {
                    const uint32_t* bh = &bH[nt >> 1][(nt & 1) * 2];
                    const uint32_t* bl = &bL[nt >> 1][(nt & 1) * 2];
                    mma_f16(acc[mt][nt], aH[mt], bh);
                    mma_f16(acc[mt][nt], aH[mt], bl);
                    mma_f16(acc[mt][nt], aL[mt], bh);
                }
            }
        }
        __syncthreads();
    }

    // Epilogue
    const int rl = lane >> 2;
    const int cl = 2 * (lane & 3);
#pragma unroll
    for (int mt = 0; mt < 4; mt++) {
#pragma unroll
        for (int nt = 0; nt < 4; nt++) {
            const int n = bn * 128 + wn * 32 + nt * 8 + cl;
            const float b0 = bias[n], b1 = bias[n + 1];
#pragma unroll
            for (int hf = 0; hf < 2; hf++) {
                const int m = bm * 128 + wm * 64 + mt * 16 + rl + hf * 8;
                const float vx = acc[mt][nt][hf * 2 + 0] + b0;
                const float vy = acc[mt][nt][hf * 2 + 1] + b1;
                const int h  = n >> 6;
                const int dk = n & 63;
                const int bb = m >> 11;
                const int ss = m & 2047;
                if (OUTMODE == 2) {
                    *(float2*)(out32 + (size_t)m * D_ + n) = make_float2(vx, vy);
                } else if (OUTMODE == 0) {
                    const size_t idx = ((size_t)((bb*H_ + h)*S_ + ss))*DK_ + dk;
                    uint32_t hp, lp;
                    split_pack2(vx, vy, hp, lp);
                    *(uint32_t*)(outh + idx) = hp;
                    *(uint32_t*)(outl + idx) = lp;
                } else {
                    const size_t idx = ((size_t)((bb*H_ + h)*DK_ + dk))*S_ + ss;
                    uint16_t hx, lx, hy, ly;
                    split_f16(vx, hx, lx);
                    split_f16(vy, hy, ly);
                    outh[idx] = hx;        outl[idx] = lx;
                    outh[idx + S_] = hy;   outl[idx + S_] = ly;
                }
            }
        }
    }
}

// ---------------------------------------------------------------------------
// Tensor-core flash attention (fp16), cp.async pipeline, register P,
// bitmask mask with all-ones fast path, PV = 2 MMAs (P single digit).
// ---------------------------------------------------------------------------
#define QKROWB 144
#define VTROWB 272
#define QK_BYTES (128 * QKROWB)
#define VT_BYTES (64 * VTROWB)
#define FQ_H  0
#define FQ_L  QK_BYTES
#define FSTG0 (2 * QK_BYTES)
#define SG_KH 0
#define SG_KL QK_BYTES
#define SG_VH (2 * QK_BYTES)
#define SG_VL (2 * QK_BYTES + VT_BYTES)
#define STG_B (2 * QK_BYTES + 2 * VT_BYTES)
#define F_SMEM (FSTG0 + 2 * STG_B)

__global__ __launch_bounds__(256, 1)
void flash_mma_kernel()
{
    extern __shared__ char dsm[];
    const uint32_t sb = smem_u32(dsm);

    const int tid  = threadIdx.x;
    const int lane = tid & 31;
    const int warp = tid >> 5;
    const int qb   = blockIdx.x;
    const int bh   = blockIdx.y;
    const int q0   = qb * 128;

    const int arow = (lane & 7) + ((lane >> 3) & 1) * 8;
    const int acol = ((lane >> 4) & 1) * 8;
    const int brow = (lane & 7) + ((lane >> 4) & 1) * 8;
    const int bcol = ((lane >> 3) & 1) * 8;
    const int ln2  = lane & 3;
    const int r0   = warp * 16 + (lane >> 2);

    const unsigned short* Qhp = p_qh + (size_t)bh * S_ * DK_;
    const unsigned short* Qlp = p_ql + (size_t)bh * S_ * DK_;
    const unsigned short* Khp = p_kh + (size_t)bh * S_ * DK_;
    const unsigned short* Klp = p_kl + (size_t)bh * S_ * DK_;
    const unsigned short* Vhp = p_vth + (size_t)bh * DK_ * S_;
    const unsigned short* Vlp = p_vtl + (size_t)bh * DK_ * S_;

    const int row  = tid >> 1, seg  = tid & 1;
    const int vrow = tid >> 2, vseg = tid & 3;

    auto load_kv = [&](int t0, int buf) {
        const uint32_t st = sb + FSTG0 + (uint32_t)buf * STG_B;
        const size_t g = (size_t)(t0 + row) * DK_ + seg * 32;
        const uint32_t s = st + row * QKROWB + seg * 64;
#pragma unroll
        for (int i = 0; i < 4; i++) {
            cp16(s + SG_KH + i*16, Khp + g + i*8);
            cp16(s + SG_KL + i*16, Klp + g + i*8);
        }
        const size_t gv = (size_t)vrow * S_ + t0 + vseg * 32;
        const uint32_t sv = st + vrow * VTROWB + vseg * 64;
#pragma unroll
        for (int i = 0; i < 4; i++) {
            cp16(sv + SG_VH + i*16, Vhp + gv + i*8);
            cp16(sv + SG_VL + i*16, Vlp + gv + i*8);
        }
    };

    {
        const size_t g = (size_t)(q0 + row) * DK_ + seg * 32;
        const uint32_t s = sb + row * QKROWB + seg * 64;
#pragma unroll
        for (int i = 0; i < 4; i++) {
            cp16(s + FQ_H + i*16, Qhp + g + i*8);
            cp16(s + FQ_L + i*16, Qlp + g + i*8);
        }
    }
    load_kv(0, 0);
    CP_COMMIT();

    float m0 = -1e30f, m1 = -1e30f, l0 = 0.f, l1 = 0.f;
    float oacc[8][4];
#pragma unroll
    for (int j = 0; j < 8; j++)
#pragma unroll
        for (int e = 0; e < 4; e++) oacc[j][e] = 0.f;

    for (int it = 0; it < 16; it++) {
        const int buf = it & 1;
        if (it < 15) {
            load_kv((it + 1) * 128, 1 - buf);
            CP_COMMIT();
            CP_WAIT(1);
        } else {
            CP_WAIT(0);
        }
        __syncthreads();
        const uint32_t st = sb + FSTG0 + (uint32_t)buf * STG_B;

        // ---- S = Q K^T (3-term fp16)
        float sacc[16][4];
#pragma unroll
        for (int j = 0; j < 16; j++)
#pragma unroll
            for (int e = 0; e < 4; e++) sacc[j][e] = 0.f;

#pragma unroll
        for (int ks = 0; ks < 4; ks++) {
            const uint32_t kb = (uint32_t)(ks * 32);
            uint32_t aH[4], aL[4];
            const uint32_t ao = sb + (warp*16 + arow) * QKROWB + acol*2 + kb;
            ldsm_x4(aH, ao + FQ_H);
            ldsm_x4(aL, ao + FQ_L);
#pragma unroll
            for (int j16 = 0; j16 < 8; j16++) {
                uint32_t bH[4], bL[4];
                const uint32_t bo = st + (j16*16 + brow) * QKROWB + bcol*2 + kb;
                ldsm_x4(bH, bo + SG_KH);
                ldsm_x4(bL, bo + SG_KL);
#pragma unroll
                for (int hf = 0; hf < 2; hf++) {
                    float* a2 = sacc[j16*2 + hf];
                    mma_f16(a2, aH, &bH[hf*2]);
                    mma_f16(a2, aH, &bL[hf*2]);
                    mma_f16(a2, aL, &bH[hf*2]);
                }
            }
        }

        // ---- mask (bitmask) + online softmax; P stays in registers
#pragma unroll
        for (int p = 0; p < 2; p++) {
            const int r  = r0 + p * 8;
            const int eb = p * 2;
            const uint4 mw = ((const uint4*)m_bits)[(size_t)(q0 + r) * 16 + it];
            const bool allset =
                (mw.x & mw.y & mw.z & mw.w) == 0xffffffffu;

            float mx = -1e30f;
            if (allset) {
#pragma unroll
                for (int j = 0; j < 16; j++) {
                    const float v0 = sacc[j][eb+0] * 0.125f;
                    const float v1 = sacc[j][eb+1] * 0.125f;
                    sacc[j][eb+0] = v0;
                    sacc[j][eb+1] = v1;
                    mx = fmaxf(mx, fmaxf(v0, v1));
                }
            } else {
                const uint32_t ws[4] = {mw.x, mw.y, mw.z, mw.w};
#pragma unroll
                for (int j = 0; j < 16; j++) {
                    const uint32_t wj = ws[j >> 2];
                    const int bit0 = (j & 3) * 8 + 2 * ln2;
                    float v0 = sacc[j][eb+0] * 0.125f;
                    float v1 = sacc[j][eb+1] * 0.125f;
                    if (!((wj >> bit0) & 1u))       v0 = -1e9f;
                    if (!((wj >> (bit0 + 1)) & 1u)) v1 = -1e9f;
                    sacc[j][eb+0] = v0;
                    sacc[j][eb+1] = v1;
                    mx = fmaxf(mx, fmaxf(v0, v1));
                }
            }
            mx = fmaxf(mx, __shfl_xor_sync(0xffffffffu, mx, 1));
            mx = fmaxf(mx, __shfl_xor_sync(0xffffffffu, mx, 2));

            const float mp   = (p == 0) ? m0 : m1;
            const float mnew = fmaxf(mp, mx);
            const float corr = __expf(mp - mnew);
            float sum = 0.f;
#pragma unroll
            for (int j = 0; j < 16; j++) {
                const float p0 = __expf(sacc[j][eb+0] - mnew);
                const float p1 = __expf(sacc[j][eb+1] - mnew);
                sacc[j][eb+0] = p0;
                sacc[j][eb+1] = p1;
                sum += p0 + p1;
            }
            sum += __shfl_xor_sync(0xffffffffu, sum, 1);
            sum += __shfl_xor_sync(0xffffffffu, sum, 2);

            if (p == 0) { l0 = l0 * corr + sum; m0 = mnew; }
            else        { l1 = l1 * corr + sum; m1 = mnew; }
#pragma unroll
            for (int j = 0; j < 8; j++) {
                oacc[j][eb+0] *= corr;
                oacc[j][eb+1] *= corr;
            }
        }

        // ---- O += P V : P single fp16 digit, V 2 digits (2 MMAs)
#pragma unroll
        for (int ks = 0; ks < 8; ks++) {
            uint32_t aP[4];
            aP[0] = pack_h2(sacc[2*ks  ][0], sacc[2*ks  ][1]);
            aP[1] = pack_h2(sacc[2*ks  ][2], sacc[2*ks  ][3]);
            aP[2] = pack_h2(sacc[2*ks+1][0], sacc[2*ks+1][1]);
            aP[3] = pack_h2(sacc[2*ks+1][2], sacc[2*ks+1][3]);
            const uint32_t kb = (uint32_t)(ks * 32);
#pragma unroll
            for (int j16 = 0; j16 < 4; j16++) {
                uint32_t bH[4], bL[4];
                const uint32_t bo = st + (j16*16 + brow) * VTROWB + bcol*2 + kb;
                ldsm_x4(bH, bo + SG_VH);
                ldsm_x4(bL, bo + SG_VL);
#pragma unroll
                for (int hf = 0; hf < 2; hf++) {
                    float* a2 = oacc[j16*2 + hf];
                    mma_f16(a2, aP, &bH[hf*2]);
                    mma_f16(a2, aP, &bL[hf*2]);
                }
            }
        }
        __syncthreads();
    }

    // ---- epilogue: X[b][s][h*64+dk] fp16 hi/lo
    const int bb = bh >> 4, hh = bh & 15;
#pragma unroll
    for (int p = 0; p < 2; p++) {
        const int r   = r0 + p * 8;
        const int eb  = p * 2;
        const float inv = 1.f / ((p == 0) ? l0 : l1);
        const size_t base = ((size_t)(bb * S_ + q0 + r)) * D_ + hh * DK_ + 2*ln2;
#pragma unroll
        for (int j = 0; j < 8; j++) {
            uint32_t hp, lp;
            split_pack2(oacc[j][eb+0] * inv, oacc[j][eb+1] * inv, hp, lp);
            *(uint32_t*)(x_h + base + j*8) = hp;
            *(uint32_t*)(x_l + base + j*8) = lp;
        }
    }
}

// ---------------------------------------------------------------------------
extern "C" void kernel_launch(void* const* d_in, const int* in_sizes, int n_in,
                              void* d_out, int out_size)
{
    (void)in_sizes; (void)n_in; (void)out_size;
    const float* query = (const float*)d_in[0];
    const float* key_  = (const float*)d_in[1];
    const float* value = (const float*)d_in[2];
    const int*   mask  = (const int*)  d_in[3];
    const float* Wq    = (const float*)d_in[4];
    const float* bq    = (const float*)d_in[5];
    const float* Wk    = (const float*)d_in[6];
    const float* bk    = (const float*)d_in[7];
    const float* Wv    = (const float*)d_in[8];
    const float* bv    = (const float*)d_in[9];
    const float* Wo    = (const float*)d_in[10];
    const float* bo    = (const float*)d_in[11];
    float* out = (float*)d_out;

    cudaFuncSetAttribute(flash_mma_kernel,
                         cudaFuncAttributeMaxDynamicSharedMemorySize, F_SMEM);
    cudaFuncSetAttribute(gemm_f16_kernel<0>,
                         cudaFuncAttributeMaxDynamicSharedMemorySize, GSMEM);
    cudaFuncSetAttribute(gemm_f16_kernel<1>,
                         cudaFuncAttributeMaxDynamicSharedMemorySize, GSMEM);
    cudaFuncSetAttribute(gemm_f16_kernel<2>,
                         cudaFuncAttributeMaxDynamicSharedMemorySize, GSMEM);

    void *cqh,*cql,*ckh,*ckl,*cvh,*cvl;
    void *wqh,*wql,*wkh,*wkl,*wvh,*wvl,*woh,*wol;
    void *pqh,*pql,*pkh,*pkl,*pvth,*pvtl,*xh,*xl;
    cudaGetSymbolAddress(&cqh, c_qh); cudaGetSymbolAddress(&cql, c_ql);
    cudaGetSymbolAddress(&ckh, c_kh); cudaGetSymbolAddress(&ckl, c_kl);
    cudaGetSymbolAddress(&cvh, c_vh); cudaGetSymbolAddress(&cvl, c_vl);
    cudaGetSymbolAddress(&wqh, w_qh); cudaGetSymbolAddress(&wql, w_ql);
    cudaGetSymbolAddress(&wkh, w_kh); cudaGetSymbolAddress(&wkl, w_kl);
    cudaGetSymbolAddress(&wvh, w_vh); cudaGetSymbolAddress(&wvl, w_vl);
    cudaGetSymbolAddress(&woh, w_oh); cudaGetSymbolAddress(&wol, w_ol);
    cudaGetSymbolAddress(&pqh, p_qh); cudaGetSymbolAddress(&pql, p_ql);
    cudaGetSymbolAddress(&pkh, p_kh); cudaGetSymbolAddress(&pkl, p_kl);
    cudaGetSymbolAddress(&pvth, p_vth); cudaGetSymbolAddress(&pvtl, p_vtl);
    cudaGetSymbolAddress(&xh, x_h); cudaGetSymbolAddress(&xl, x_l);

    typedef unsigned short us;

    // 1) fused convert (launch #1)
    CvtArgs ca;
    ca.in[0] = query; ca.hi[0] = (us*)cqh; ca.lo[0] = (us*)cql;
    ca.in[1] = key_;  ca.hi[1] = (us*)ckh; ca.lo[1] = (us*)ckl;
    ca.in[2] = value; ca.hi[2] = (us*)cvh; ca.lo[2] = (us*)cvl;
    ca.in[3] = Wq;    ca.hi[3] = (us*)wqh; ca.lo[3] = (us*)wql;
    ca.in[4] = Wk;    ca.hi[4] = (us*)wkh; ca.lo[4] = (us*)wkl;
    ca.in[5] = Wv;    ca.hi[5] = (us*)wvh; ca.lo[5] = (us*)wvl;
    ca.in[6] = Wo;    ca.hi[6] = (us*)woh; ca.lo[6] = (us*)wol;
    convert_all_kernel<<<dim3(512, 7), 256>>>(ca, M_*D_/4, D_*D_/4);

    // 2) projections (launches #2-#4)
    const dim3 ggrid(D_/128, M_/128);
    gemm_f16_kernel<0><<<ggrid, 256, GSMEM>>>(
        (const us*)cqh, (const us*)cql, (const us*)wqh, (const us*)wql,
        bq, nullptr, (us*)pqh, (us*)pql);
    gemm_f16_kernel<0><<<ggrid, 256, GSMEM>>>(
        (const us*)ckh, (const us*)ckl, (const us*)wkh, (const us*)wkl,
        bk, nullptr, (us*)pkh, (us*)pkl);
    gemm_f16_kernel<1><<<ggrid, 256, GSMEM>>>(
        (const us*)cvh, (const us*)cvl, (const us*)wvh, (const us*)wvl,
        bv, nullptr, (us*)pvth, (us*)pvtl);

    // 3) mask bitmask (launch #5)
    mask_bits_kernel<<<S_*S_/32/256, 256>>>(mask);

    // 4) flash attention (launch #6 — ncu -s 5 -c 1 profiles this one)
    flash_mma_kernel<<<dim3(S_/128, B_*H_), 256, F_SMEM>>>();

    // 5) output projection (launch #7)
    gemm_f16_kernel<2><<<ggrid, 256, GSMEM>>>(
        (const us*)xh, (const us*)xl, (const us*)woh, (const us*)wol,
        bo, out, nullptr, nullptr);
}

// round 10
// speedup vs baseline: 3.0712x; 1.2299x over previous
#include <cuda_runtime.h>
#include <cuda_fp16.h>
#include <cstdint>

#define B_  4
#define S_  2048
#define D_  1024
#define H_  16
#define DK_ 64
#define M_  (B_*S_)

// ---------------------------------------------------------------------------
// Scratch (fp16 bit-patterns in ushort arrays; no allocation APIs)
// ---------------------------------------------------------------------------
__device__ unsigned short c_qh[M_*D_], c_ql[M_*D_];
__device__ unsigned short c_kh[M_*D_], c_kl[M_*D_];
__device__ unsigned short c_vh[M_*D_], c_vl[M_*D_];
__device__ unsigned short w_qh[D_*D_], w_ql[D_*D_];
__device__ unsigned short w_kh[D_*D_], w_kl[D_*D_];
__device__ unsigned short w_vh[D_*D_], w_vl[D_*D_];
__device__ unsigned short w_oh[D_*D_], w_ol[D_*D_];
__device__ unsigned short p_qh[M_*D_], p_ql[M_*D_];   // Q proj, [bh][s][dk]
__device__ unsigned short p_kh[M_*D_], p_kl[M_*D_];   // K proj, [bh][s][dk]
__device__ unsigned short p_vth[M_*D_], p_vtl[M_*D_]; // V proj, [bh][dk][s]
__device__ unsigned short x_h[M_*D_], x_l[M_*D_];     // attn out, [b][s][d]
__device__ unsigned int   m_bits[S_*S_/32];           // mask bitmask

// ---------------------------------------------------------------------------
// Helpers
// ---------------------------------------------------------------------------
__device__ __forceinline__ uint32_t smem_u32(const void* p) {
    uint32_t a;
    asm("{ .reg .u64 t; cvta.to.shared.u64 t, %1; cvt.u32.u64 %0, t; }"
        : "=r"(a) : "l"(p));
    return a;
}
__device__ __forceinline__ void ldsm_x4(uint32_t* r, uint32_t addr) {
    asm volatile("ldmatrix.sync.aligned.m8n8.x4.shared.b16 {%0,%1,%2,%3}, [%4];"
                 : "=r"(r[0]), "=r"(r[1]), "=r"(r[2]), "=r"(r[3]) : "r"(addr));
}
__device__ __forceinline__ void mma_f16(float* c, const uint32_t* a,
                                        const uint32_t* b) {
    asm volatile(
        "mma.sync.aligned.m16n8k16.row.col.f32.f16.f16.f32 "
        "{%0,%1,%2,%3}, {%4,%5,%6,%7}, {%8,%9}, {%0,%1,%2,%3};"
        : "+f"(c[0]), "+f"(c[1]), "+f"(c[2]), "+f"(c[3])
        : "r"(a[0]), "r"(a[1]), "r"(a[2]), "r"(a[3]), "r"(b[0]), "r"(b[1]));
}
__device__ __forceinline__ void cp16(uint32_t dst, const void* src) {
    asm volatile("cp.async.cg.shared.global [%0], [%1], 16;"
                 :: "r"(dst), "l"(src) : "memory");
}
#define CP_COMMIT()  asm volatile("cp.async.commit_group;" ::: "memory")
#define CP_WAIT(n)   asm volatile("cp.async.wait_group %0;" :: "n"(n) : "memory")

__device__ __forceinline__ void split_f16(float x, uint16_t& h, uint16_t& l) {
    __half hb = __float2half_rn(x);
    float r = x - __half2float(hb);
    __half lb = __float2half_rn(r);
    h = __half_as_ushort(hb);
    l = __half_as_ushort(lb);
}
__device__ __forceinline__ void split_pack2(float x, float y,
                                            uint32_t& hp, uint32_t& lp) {
    uint16_t hx, lx, hy, ly;
    split_f16(x, hx, lx);
    split_f16(y, hy, ly);
    hp = (uint32_t)hx | ((uint32_t)hy << 16);
    lp = (uint32_t)lx | ((uint32_t)ly << 16);
}
__device__ __forceinline__ uint32_t pack_h2(float lo, float hi) {
    __half2 h = __floats2half2_rn(lo, hi);
    return *(uint32_t*)&h;
}

// ---------------------------------------------------------------------------
// Fused convert: 7 tensors fp32 -> (hi, lo) fp16 in one launch
// ---------------------------------------------------------------------------
struct CvtArgs {
    const float*    in[7];
    unsigned short* hi[7];
    unsigned short* lo[7];
};

__global__ void convert_all_kernel(CvtArgs args, int n4_act, int n4_w)
{
    const int z  = blockIdx.y;
    const int n4 = (z < 3) ? n4_act : n4_w;
    const float* in = args.in[z];
    unsigned short* hi = args.hi[z];
    unsigned short* lo = args.lo[z];
    const int stride = gridDim.x * blockDim.x;
    for (int i = blockIdx.x * blockDim.x + threadIdx.x; i < n4; i += stride) {
        float4 v = ((const float4*)in)[i];
        uint32_t h0, l0, h1, l1;
        split_pack2(v.x, v.y, h0, l0);
        split_pack2(v.z, v.w, h1, l1);
        ((uint2*)hi)[i] = make_uint2(h0, h1);
        ((uint2*)lo)[i] = make_uint2(l0, l1);
    }
}

// ---------------------------------------------------------------------------
// Mask -> bitmask (1 bit per entry)
// ---------------------------------------------------------------------------
__global__ void mask_bits_kernel(const int* __restrict__ mask)
{
    const int w = blockIdx.x * blockDim.x + threadIdx.x;
    if (w >= S_*S_/32) return;
    const int4* p = (const int4*)(mask + (size_t)w * 32);
    uint32_t bits = 0;
#pragma unroll
    for (int i = 0; i < 8; i++) {
        int4 v = p[i];
        bits |= (uint32_t)(v.x != 0) << (i*4 + 0);
        bits |= (uint32_t)(v.y != 0) << (i*4 + 1);
        bits |= (uint32_t)(v.z != 0) << (i*4 + 2);
        bits |= (uint32_t)(v.w != 0) << (i*4 + 3);
    }
    m_bits[w] = bits;
}

// ---------------------------------------------------------------------------
// GEMM core (fp16 split, 3-term), shared by QKV-fused and output kernels.
// CTA 128x128, BK=32, 8 warps, cp.async 2-stage.
// MODE 0: fp16 h/l head layout [bh][s][dk]
// MODE 1: fp16 h (+skip lo) transposed head layout [bh][dk][s]
// MODE 2: fp32 natural [m][n]
// ---------------------------------------------------------------------------
#define GROWB  80
#define GARR   (128 * GROWB)
#define GSTAGE (4 * GARR)
#define GSMEM  (2 * GSTAGE)              // 81920 B

__device__ __forceinline__ void gemm_core(
    const unsigned short* __restrict__ Ah,
    const unsigned short* __restrict__ Al,
    const unsigned short* __restrict__ Wh,
    const unsigned short* __restrict__ Wl,
    const float* __restrict__ bias,
    float* __restrict__ out32,
    unsigned short* __restrict__ outh,
    unsigned short* __restrict__ outl,
    int mode, int bm, int bn)
{
    extern __shared__ char dsm[];
    const uint32_t sbase = smem_u32(dsm);

    const int tid  = threadIdx.x;
    const int lane = tid & 31;
    const int warp = tid >> 5;
    const int wm   = warp >> 2;
    const int wn   = warp & 3;

    const int arow = (lane & 7) + ((lane >> 3) & 1) * 8;
    const int acol = ((lane >> 4) & 1) * 8;
    const int brow = (lane & 7) + ((lane >> 4) & 1) * 8;
    const int bcol = ((lane >> 3) & 1) * 8;

    const int r    = tid >> 1;
    const int half = tid & 1;
    const unsigned short* Ap  = Ah + (size_t)(bm * 128 + r) * D_ + half * 16;
    const unsigned short* Alp = Al + (size_t)(bm * 128 + r) * D_ + half * 16;
    const unsigned short* Wp  = Wh + (size_t)(bn * 128 + r) * D_ + half * 16;
    const unsigned short* Wlp = Wl + (size_t)(bn * 128 + r) * D_ + half * 16;
    const uint32_t st_off = (uint32_t)(r * GROWB + half * 32);

    float acc[4][4][4];
#pragma unroll
    for (int i = 0; i < 4; i++)
#pragma unroll
        for (int j = 0; j < 4; j++)
#pragma unroll
            for (int e = 0; e < 4; e++) acc[i][j][e] = 0.f;

    auto load_chunk = [&](int c, uint32_t stg) {
        const int kt = c * 32;
        const uint32_t a0 = stg + st_off;
        cp16(a0,              Ap + kt);
        cp16(a0 + 16,         Ap + kt + 8);
        cp16(a0 + GARR,       Alp + kt);
        cp16(a0 + GARR + 16,  Alp + kt + 8);
        cp16(a0 + 2*GARR,      Wp + kt);
        cp16(a0 + 2*GARR + 16, Wp + kt + 8);
        cp16(a0 + 3*GARR,      Wlp + kt);
        cp16(a0 + 3*GARR + 16, Wlp + kt + 8);
    };

    load_chunk(0, sbase);
    CP_COMMIT();

    const uint32_t aoff0 = (uint32_t)((wm * 64 + arow) * GROWB + acol * 2);
    const uint32_t boff0 = (uint32_t)((wn * 32 + brow) * GROWB + bcol * 2);

    for (int c = 0; c < 32; c++) {
        const uint32_t stg = sbase + (uint32_t)(c & 1) * GSTAGE;
        if (c < 31) {
            load_chunk(c + 1, sbase + (uint32_t)((c + 1) & 1) * GSTAGE);
            CP_COMMIT();
            CP_WAIT(1);
        } else {
            CP_WAIT(0);
        }
        __syncthreads();

#pragma unroll
        for (int ks = 0; ks < 2; ks++) {
            const uint32_t kb = (uint32_t)(ks * 32);
            uint32_t aH[4][4], aL[4][4];
#pragma unroll
            for (int mt = 0; mt < 4; mt++) {
                const uint32_t ao = stg + aoff0 + (uint32_t)(mt*16*GROWB) + kb;
                ldsm_x4(aH[mt], ao);
                ldsm_x4(aL[mt], ao + GARR);
            }
            uint32_t bH[2][4], bL[2][4];
#pragma unroll
            for (int ng = 0; ng < 2; ng++) {
                const uint32_t bo = stg + 2*GARR + boff0
                                  + (uint32_t)(ng*16*GROWB) + kb;
                ldsm_x4(bH[ng], bo);
                ldsm_x4(bL[ng], bo + GARR);
            }
#pragma unroll
            for (int mt = 0; mt < 4; mt++) {
#pragma unroll
                for (int nt = 0; nt < 4; nt++) {
                    const uint32_t* bh = &bH[nt >> 1][(nt & 1) * 2];
                    const uint32_t* bl = &bL[nt >> 1][(nt & 1) * 2];
                    mma_f16(acc[mt][nt], aH[mt], bh);
                    mma_f16(acc[mt][nt], aH[mt], bl);
                    mma_f16(acc[mt][nt], aL[mt], bh);
                }
            }
        }
        __syncthreads();
    }

    // Epilogue
    const int rl = lane >> 2;
    const int cl = 2 * (lane & 3);
#pragma unroll
    for (int mt = 0; mt < 4; mt++) {
#pragma unroll
        for (int nt = 0; nt < 4; nt++) {
            const int n = bn * 128 + wn * 32 + nt * 8 + cl;
            const float b0 = bias[n], b1 = bias[n + 1];
#pragma unroll
            for (int hf = 0; hf < 2; hf++) {
                const int m = bm * 128 + wm * 64 + mt * 16 + rl + hf * 8;
                const float vx = acc[mt][nt][hf * 2 + 0] + b0;
                const float vy = acc[mt][nt][hf * 2 + 1] + b1;
                const int h  = n >> 6;
                const int dk = n & 63;
                const int bb = m >> 11;
                const int ss = m & 2047;
                if (mode == 2) {
                    *(float2*)(out32 + (size_t)m * D_ + n) = make_float2(vx, vy);
                } else if (mode == 0) {
                    const size_t idx = ((size_t)((bb*H_ + h)*S_ + ss))*DK_ + dk;
                    uint32_t hp, lp;
                    split_pack2(vx, vy, hp, lp);
                    *(uint32_t*)(outh + idx) = hp;
                    *(uint32_t*)(outl + idx) = lp;
                } else {
                    // transposed, hi digit only (flash uses single-digit V)
                    const size_t idx = ((size_t)((bb*H_ + h)*DK_ + dk))*S_ + ss;
                    outh[idx]      = __half_as_ushort(__float2half_rn(vx));
                    outh[idx + S_] = __half_as_ushort(__float2half_rn(vy));
                }
            }
        }
    }
}

struct QKVArgs {
    const unsigned short* Ah[3];
    const unsigned short* Al[3];
    const unsigned short* Wh[3];
    const unsigned short* Wl[3];
    const float*          bias[3];
    unsigned short*       outh[3];
    unsigned short*       outl[3];
};

__global__ __launch_bounds__(256)
void gemm_qkv_kernel(QKVArgs a)
{
    const int z = blockIdx.z;
    gemm_core(a.Ah[z], a.Al[z], a.Wh[z], a.Wl[z], a.bias[z],
              nullptr, a.outh[z], a.outl[z],
              (z == 2) ? 1 : 0, blockIdx.y, blockIdx.x);
}

__global__ __launch_bounds__(256)
void gemm_out_kernel(const unsigned short* Ah, const unsigned short* Al,
                     const unsigned short* Wh, const unsigned short* Wl,
                     const float* bias, float* out32)
{
    gemm_core(Ah, Al, Wh, Wl, bias, out32, nullptr, nullptr,
              2, blockIdx.y, blockIdx.x);
}

// ---------------------------------------------------------------------------
// Tensor-core flash attention: Q 2-digit, K 1-digit, V 1-digit.
// S = (Qh+Ql)·Kh (2 MMAs), PV = P·Vh (1 MMA). 2 CTAs/SM.
// ---------------------------------------------------------------------------
#define QKROWB 144
#define VTROWB 272
#define QK_BYTES (128 * QKROWB)          // 18432
#define VT_BYTES (64 * VTROWB)           // 17408
#define FQ_H  0
#define FQ_L  QK_BYTES
#define FSTG0 (2 * QK_BYTES)             // 36864
#define SG_KH 0
#define SG_VH QK_BYTES
#define STG_B (QK_BYTES + VT_BYTES)      // 35840
#define F_SMEM (FSTG0 + 2 * STG_B)       // 108544

__global__ __launch_bounds__(256, 2)
void flash_mma_kernel()
{
    extern __shared__ char dsm[];
    const uint32_t sb = smem_u32(dsm);

    const int tid  = threadIdx.x;
    const int lane = tid & 31;
    const int warp = tid >> 5;
    const int qb   = blockIdx.x;
    const int bh   = blockIdx.y;
    const int q0   = qb * 128;

    const int arow = (lane & 7) + ((lane >> 3) & 1) * 8;
    const int acol = ((lane >> 4) & 1) * 8;
    const int brow = (lane & 7) + ((lane >> 4) & 1) * 8;
    const int bcol = ((lane >> 3) & 1) * 8;
    const int ln2  = lane & 3;
    const int r0   = warp * 16 + (lane >> 2);

    const unsigned short* Qhp = p_qh + (size_t)bh * S_ * DK_;
    const unsigned short* Qlp = p_ql + (size_t)bh * S_ * DK_;
    const unsigned short* Khp = p_kh + (size_t)bh * S_ * DK_;
    const unsigned short* Vhp = p_vth + (size_t)bh * DK_ * S_;

    const int row  = tid >> 1, seg  = tid & 1;
    const int vrow = tid >> 2, vseg = tid & 3;

    auto load_kv = [&](int t0, int buf) {
        const uint32_t st = sb + FSTG0 + (uint32_t)buf * STG_B;
        const size_t g = (size_t)(t0 + row) * DK_ + seg * 32;
        const uint32_t s = st + row * QKROWB + seg * 64;
#pragma unroll
        for (int i = 0; i < 4; i++)
            cp16(s + SG_KH + i*16, Khp + g + i*8);
        const size_t gv = (size_t)vrow * S_ + t0 + vseg * 32;
        const uint32_t sv = st + vrow * VTROWB + vseg * 64;
#pragma unroll
        for (int i = 0; i < 4; i++)
            cp16(sv + SG_VH + i*16, Vhp + gv + i*8);
    };

    {
        const size_t g = (size_t)(q0 + row) * DK_ + seg * 32;
        const uint32_t s = sb + row * QKROWB + seg * 64;
#pragma unroll
        for (int i = 0; i < 4; i++) {
            cp16(s + FQ_H + i*16, Qhp + g + i*8);
            cp16(s + FQ_L + i*16, Qlp + g + i*8);
        }
    }
    load_kv(0, 0);
    CP_COMMIT();

    float m0 = -1e30f, m1 = -1e30f, l0 = 0.f, l1 = 0.f;
    float oacc[8][4];
#pragma unroll
    for (int j = 0; j < 8; j++)
#pragma unroll
        for (int e = 0; e < 4; e++) oacc[j][e] = 0.f;

    for (int it = 0; it < 16; it++) {
        const int buf = it & 1;
        if (it < 15) {
            load_kv((it + 1) * 128, 1 - buf);
            CP_COMMIT();
            CP_WAIT(1);
        } else {
            CP_WAIT(0);
        }
        __syncthreads();
        const uint32_t st = sb + FSTG0 + (uint32_t)buf * STG_B;

        // ---- S = Q K^T (Q 2-digit, K 1-digit)
        float sacc[16][4];
#pragma unroll
        for (int j = 0; j < 16; j++)
#pragma unroll
            for (int e = 0; e < 4; e++) sacc[j][e] = 0.f;

#pragma unroll
        for (int ks = 0; ks < 4; ks++) {
            const uint32_t kb = (uint32_t)(ks * 32);
            uint32_t aH[4], aL[4];
            const uint32_t ao = sb + (warp*16 + arow) * QKROWB + acol*2 + kb;
            ldsm_x4(aH, ao + FQ_H);
            ldsm_x4(aL, ao + FQ_L);
#pragma unroll
            for (int j16 = 0; j16 < 8; j16++) {
                uint32_t bH[4];
                const uint32_t bo = st + (j16*16 + brow) * QKROWB + bcol*2 + kb;
                ldsm_x4(bH, bo + SG_KH);
#pragma unroll
                for (int hf = 0; hf < 2; hf++) {
                    float* a2 = sacc[j16*2 + hf];
                    mma_f16(a2, aH, &bH[hf*2]);
                    mma_f16(a2, aL, &bH[hf*2]);
                }
            }
        }

        // ---- mask (bitmask) + online softmax; P stays in registers
#pragma unroll
        for (int p = 0; p < 2; p++) {
            const int r  = r0 + p * 8;
            const int eb = p * 2;
            const uint4 mw = ((const uint4*)m_bits)[(size_t)(q0 + r) * 16 + it];
            const bool allset =
                (mw.x & mw.y & mw.z & mw.w) == 0xffffffffu;

            float mx = -1e30f;
            if (allset) {
#pragma unroll
                for (int j = 0; j < 16; j++) {
                    const float v0 = sacc[j][eb+0] * 0.125f;
                    const float v1 = sacc[j][eb+1] * 0.125f;
                    sacc[j][eb+0] = v0;
                    sacc[j][eb+1] = v1;
                    mx = fmaxf(mx, fmaxf(v0, v1));
                }
            } else {
                const uint32_t ws[4] = {mw.x, mw.y, mw.z, mw.w};
#pragma unroll
                for (int j = 0; j < 16; j++) {
                    const uint32_t wj = ws[j >> 2];
                    const int bit0 = (j & 3) * 8 + 2 * ln2;
                    float v0 = sacc[j][eb+0] * 0.125f;
                    float v1 = sacc[j][eb+1] * 0.125f;
                    if (!((wj >> bit0) & 1u))       v0 = -1e9f;
                    if (!((wj >> (bit0 + 1)) & 1u)) v1 = -1e9f;
                    sacc[j][eb+0] = v0;
                    sacc[j][eb+1] = v1;
                    mx = fmaxf(mx, fmaxf(v0, v1));
                }
            }
            mx = fmaxf(mx, __shfl_xor_sync(0xffffffffu, mx, 1));
            mx = fmaxf(mx, __shfl_xor_sync(0xffffffffu, mx, 2));

            const float mp   = (p == 0) ? m0 : m1;
            const float mnew = fmaxf(mp, mx);
            const float corr = __expf(mp - mnew);
            float sum = 0.f;
#pragma unroll
            for (int j = 0; j < 16; j++) {
                const float p0 = __expf(sacc[j][eb+0] - mnew);
                const float p1 = __expf(sacc[j][eb+1] - mnew);
                sacc[j][eb+0] = p0;
                sacc[j][eb+1] = p1;
                sum += p0 + p1;
            }
            sum += __shfl_xor_sync(0xffffffffu, sum, 1);
            sum += __shfl_xor_sync(0xffffffffu, sum, 2);

            if (p == 0) { l0 = l0 * corr + sum; m0 = mnew; }
            else        { l1 = l1 * corr + sum; m1 = mnew; }
#pragma unroll
            for (int j = 0; j < 8; j++) {
                oacc[j][eb+0] *= corr;
                oacc[j][eb+1] *= corr;
            }
        }

        // ---- O += P V (V 1-digit)
#pragma unroll
        for (int ks = 0; ks < 8; ks++) {
            uint32_t aP[4];
            aP[0] = pack_h2(sacc[2*ks  ][0], sacc[2*ks  ][1]);
            aP[1] = pack_h2(sacc[2*ks  ][2], sacc[2*ks  ][3]);
            aP[2] = pack_h2(sacc[2*ks+1][0], sacc[2*ks+1][1]);
            aP[3] = pack_h2(sacc[2*ks+1][2], sacc[2*ks+1][3]);
            const uint32_t kb = (uint32_t)(ks * 32);
#pragma unroll
            for (int j16 = 0; j16 < 4; j16++) {
                uint32_t bH[4];
                const uint32_t bo = st + (j16*16 + brow) * VTROWB + bcol*2 + kb;
                ldsm_x4(bH, bo + SG_VH);
                mma_f16(oacc[j16*2 + 0], aP, &bH[0]);
                mma_f16(oacc[j16*2 + 1], aP, &bH[2]);
            }
        }
        __syncthreads();
    }

    // ---- epilogue: X[b][s][h*64+dk] fp16 hi/lo
    const int bb = bh >> 4, hh = bh & 15;
#pragma unroll
    for (int p = 0; p < 2; p++) {
        const int r   = r0 + p * 8;
        const int eb  = p * 2;
        const float inv = 1.f / ((p == 0) ? l0 : l1);
        const size_t base = ((size_t)(bb * S_ + q0 + r)) * D_ + hh * DK_ + 2*ln2;
#pragma unroll
        for (int j = 0; j < 8; j++) {
            uint32_t hp, lp;
            split_pack2(oacc[j][eb+0] * inv, oacc[j][eb+1] * inv, hp, lp);
            *(uint32_t*)(x_h + base + j*8) = hp;
            *(uint32_t*)(x_l + base + j*8) = lp;
        }
    }
}

// ---------------------------------------------------------------------------
extern "C" void kernel_launch(void* const* d_in, const int* in_sizes, int n_in,
                              void* d_out, int out_size)
{
    (void)in_sizes; (void)n_in; (void)out_size;
    const float* query = (const float*)d_in[0];
    const float* key_  = (const float*)d_in[1];
    const float* value = (const float*)d_in[2];
    const int*   mask  = (const int*)  d_in[3];
    const float* Wq    = (const float*)d_in[4];
    const float* bq    = (const float*)d_in[5];
    const float* Wk    = (const float*)d_in[6];
    const float* bk    = (const float*)d_in[7];
    const float* Wv    = (const float*)d_in[8];
    const float* bv    = (const float*)d_in[9];
    const float* Wo    = (const float*)d_in[10];
    const float* bo    = (const float*)d_in[11];
    float* out = (float*)d_out;

    cudaFuncSetAttribute(flash_mma_kernel,
                         cudaFuncAttributeMaxDynamicSharedMemorySize, F_SMEM);
    cudaFuncSetAttribute(gemm_qkv_kernel,
                         cudaFuncAttributeMaxDynamicSharedMemorySize, GSMEM);
    cudaFuncSetAttribute(gemm_out_kernel,
                         cudaFuncAttributeMaxDynamicSharedMemorySize, GSMEM);

    void *cqh,*cql,*ckh,*ckl,*cvh,*cvl;
    void *wqh,*wql,*wkh,*wkl,*wvh,*wvl,*woh,*wol;
    void *pqh,*pql,*pkh,*pkl,*pvth,*pvtl,*xh,*xl;
    cudaGetSymbolAddress(&cqh, c_qh); cudaGetSymbolAddress(&cql, c_ql);
    cudaGetSymbolAddress(&ckh, c_kh); cudaGetSymbolAddress(&ckl, c_kl);
    cudaGetSymbolAddress(&cvh, c_vh); cudaGetSymbolAddress(&cvl, c_vl);
    cudaGetSymbolAddress(&wqh, w_qh); cudaGetSymbolAddress(&wql, w_ql);
    cudaGetSymbolAddress(&wkh, w_kh); cudaGetSymbolAddress(&wkl, w_kl);
    cudaGetSymbolAddress(&wvh, w_vh); cudaGetSymbolAddress(&wvl, w_vl);
    cudaGetSymbolAddress(&woh, w_oh); cudaGetSymbolAddress(&wol, w_ol);
    cudaGetSymbolAddress(&pqh, p_qh); cudaGetSymbolAddress(&pql, p_ql);
    cudaGetSymbolAddress(&pkh, p_kh); cudaGetSymbolAddress(&pkl, p_kl);
    cudaGetSymbolAddress(&pvth, p_vth); cudaGetSymbolAddress(&pvtl, p_vtl);
    cudaGetSymbolAddress(&xh, x_h); cudaGetSymbolAddress(&xl, x_l);

    typedef unsigned short us;

    // 1) fused convert
    CvtArgs ca;
    ca.in[0] = query; ca.hi[0] = (us*)cqh; ca.lo[0] = (us*)cql;
    ca.in[1] = key_;  ca.hi[1] = (us*)ckh; ca.lo[1] = (us*)ckl;
    ca.in[2] = value; ca.hi[2] = (us*)cvh; ca.lo[2] = (us*)cvl;
    ca.in[3] = Wq;    ca.hi[3] = (us*)wqh; ca.lo[3] = (us*)wql;
    ca.in[4] = Wk;    ca.hi[4] = (us*)wkh; ca.lo[4] = (us*)wkl;
    ca.in[5] = Wv;    ca.hi[5] = (us*)wvh; ca.lo[5] = (us*)wvl;
    ca.in[6] = Wo;    ca.hi[6] = (us*)woh; ca.lo[6] = (us*)wol;
    convert_all_kernel<<<dim3(512, 7), 256>>>(ca, M_*D_/4, D_*D_/4);

    // 2) mask bitmask
    mask_bits_kernel<<<S_*S_/32/256, 256>>>(mask);

    // 3) fused Q/K/V projections (one launch, z = 3)
    QKVArgs qa;
    qa.Ah[0] = (const us*)cqh; qa.Al[0] = (const us*)cql;
    qa.Wh[0] = (const us*)wqh; qa.Wl[0] = (const us*)wql;
    qa.bias[0] = bq; qa.outh[0] = (us*)pqh; qa.outl[0] = (us*)pql;
    qa.Ah[1] = (const us*)ckh; qa.Al[1] = (const us*)ckl;
    qa.Wh[1] = (const us*)wkh; qa.Wl[1] = (const us*)wkl;
    qa.bias[1] = bk; qa.outh[1] = (us*)pkh; qa.outl[1] = (us*)pkl;
    qa.Ah[2] = (const us*)cvh; qa.Al[2] = (const us*)cvl;
    qa.Wh[2] = (const us*)wvh; qa.Wl[2] = (const us*)wvl;
    qa.bias[2] = bv; qa.outh[2] = (us*)pvth; qa.outl[2] = (us*)pvtl;
    gemm_qkv_kernel<<<dim3(D_/128, M_/128, 3), 256, GSMEM>>>(qa);

    // 4) flash attention (2 CTAs/SM)
    flash_mma_kernel<<<dim3(S_/128, B_*H_), 256, F_SMEM>>>();

    // 5) output projection
    gemm_out_kernel<<<dim3(D_/128, M_/128), 256, GSMEM>>>(
        (const us*)xh, (const us*)xl, (const us*)woh, (const us*)wol,
        bo, out);
}